// round 14
// baseline (speedup 1.0000x reference)
#include <cuda_runtime.h>
#include <cuda_fp16.h>
#include <cstdint>
#include <math.h>

#define GG 8
#define MM 1024
#define NN 8192
#define HH 256
#define NHEADS 8
#define HDIM 32
#define FFND 1024
#define QKVD 768

// ---------------- scratch ----------------
__device__ float    g_dinv[NN];
__device__ float    g_xw  [NN * HH];
__device__ float    g_xl  [NN * HH];
__device__ uint32_t g_adj [GG * MM * 32];
__device__ uint32_t g_R2  [GG * MM * 32];
__device__ uint32_t g_R3  [GG * MM * 32];
__device__ uint32_t g_R4  [GG * MM * 32];
__device__ uint32_t g_R5  [GG * MM * 32];
__device__ unsigned char g_dist[(size_t)GG * MM * MM];
__device__ float    g_qkv [(size_t)NN * QKVD];
__device__ float    g_tmp [NN * HH];
__device__ float    g_h1  [NN * HH];
__device__ float    g_h2  [NN * HH];
__device__ float    g_y   [NN * HH];
__device__ int      g_cnt [NN];
__device__ int      g_base[NN];
__device__ int      g_fillp[NN];
__device__ int      g_esrc[262144];

#define AL16 __align__(16)
__device__ AL16 __half g_x_h [NN * HH];
__device__ AL16 __half g_at_h[NN * HH];
__device__ AL16 __half g_h1_h[NN * HH];
__device__ AL16 __half g_y_h [NN * HH];
__device__ AL16 __half g_mid_h[(size_t)NN * FFND];
__device__ AL16 __half g_q_h [NN * HH];
__device__ AL16 __half g_k_h [NN * HH];
__device__ AL16 __half g_vt_h[GG * NHEADS * HDIM * MM];
__device__ AL16 __half g_whi[1376256];
#define OFF_GCN   0
#define OFF_QKV   65536
#define OFF_PROJ  262144
#define OFF_FFN1  327680
#define OFF_FFN2  589824
#define OFF_OFFN1 851968
#define OFF_OFFN2 1114112

// ---------------- helpers ----------------
__device__ __forceinline__ uint32_t packh(float a, float b) {
    uint32_t r;
    asm("cvt.rn.f16x2.f32 %0, %1, %2;" : "=r"(r) : "f"(b), "f"(a));
    return r;
}
__device__ __forceinline__ float ex2f(float x) {
    float y; asm("ex2.approx.f32 %0, %1;" : "=f"(y) : "f"(x)); return y;
}
#define CP16(dst, src) asm volatile("cp.async.cg.shared.global [%0], [%1], 16;\n" :: "r"(dst), "l"(src))
#define MMAH(d, a0, a1, a2, a3, b0, b1) \
    asm volatile("mma.sync.aligned.m16n8k16.row.col.f32.f16.f16.f32 " \
                 "{%0,%1,%2,%3}, {%4,%5,%6,%7}, {%8,%9}, {%0,%1,%2,%3};" \
                 : "+f"(d[0]), "+f"(d[1]), "+f"(d[2]), "+f"(d[3]) \
                 : "r"(a0), "r"(a1), "r"(a2), "r"(a3), "r"(b0), "r"(b1))
// fp16-accumulate variant (2 output regs = 4 halves)
#define MMAH16(c0, c1, a0, a1, a2, a3, b0, b1) \
    asm volatile("mma.sync.aligned.m16n8k16.row.col.f16.f16.f16.f16 " \
                 "{%0,%1}, {%2,%3,%4,%5}, {%6,%7}, {%0,%1};" \
                 : "+r"(c0), "+r"(c1) \
                 : "r"(a0), "r"(a1), "r"(a2), "r"(a3), "r"(b0), "r"(b1))
#define LDSM4(r0, r1, r2, r3, addr) \
    asm volatile("ldmatrix.sync.aligned.m8n8.x4.shared.b16 {%0,%1,%2,%3}, [%4];" \
                 : "=r"(r0), "=r"(r1), "=r"(r2), "=r"(r3) : "r"(addr))

// ---------------- splits (plain fp16 cast) ----------------
__global__ void splitx(const float4* __restrict__ in, __half* __restrict__ hi, int n4) {
    int i = blockIdx.x * blockDim.x + threadIdx.x;
    if (i >= n4) return;
    float4 v = in[i];
    *(uint2*)(hi + i * 4) = make_uint2(packh(v.x, v.y), packh(v.z, v.w));
}
__global__ void splitw(const float4* w0, const float4* w1, const float4* w2, const float4* w3,
                       const float4* w4, const float4* w5, const float4* w6,
                       __half* __restrict__ hi) {
    int i = blockIdx.x * blockDim.x + threadIdx.x;
    if (i >= 344064) return;
    const float4* src; int base;
    if      (i < 16384)  { src = w0; base = 0; }
    else if (i < 65536)  { src = w1; base = 16384; }
    else if (i < 81920)  { src = w2; base = 65536; }
    else if (i < 147456) { src = w3; base = 81920; }
    else if (i < 212992) { src = w4; base = 147456; }
    else if (i < 278528) { src = w5; base = 212992; }
    else                 { src = w6; base = 278528; }
    float4 v = src[i - base];
    *(uint2*)(hi + (size_t)i * 4) = make_uint2(packh(v.x, v.y), packh(v.z, v.w));
}

// ---------------- graph prep ----------------
__global__ void zero_prep(int* __restrict__ cnt, uint32_t* __restrict__ adj) {
    int i = blockIdx.x * blockDim.x + threadIdx.x;
    if (i < GG * MM * 32) adj[i] = 0u;
    if (i < NN) cnt[i] = 0;
}
__global__ void edge_prep(const int* __restrict__ ei, int E, int* __restrict__ cnt,
                          uint32_t* __restrict__ adj) {
    int e = blockIdx.x * blockDim.x + threadIdx.x;
    if (e >= E) return;
    int s = ei[e], d = ei[E + e];
    atomicAdd(&cnt[d], 1);
    if (s == d || (s >> 10) != (d >> 10)) return;
    int g = s >> 10, ls = s & 1023, ld = d & 1023;
    atomicOr(&adj[((size_t)g * MM + ls) * 32 + (ld >> 5)], 1u << (ld & 31));
    atomicOr(&adj[((size_t)g * MM + ld) * 32 + (ls >> 5)], 1u << (ls & 31));
}
__global__ void scan_kernel(const int* __restrict__ cnt, int* __restrict__ base,
                            int* __restrict__ fillp, float* __restrict__ dinv) {
    __shared__ int wsum[32];
    int t = threadIdx.x;
    int v[8]; int s = 0;
#pragma unroll
    for (int k = 0; k < 8; ++k) { v[k] = s; s += cnt[t * 8 + k]; }
    int lane = t & 31, w = t >> 5;
    int tot = s, sc = s;
#pragma unroll
    for (int o = 1; o < 32; o <<= 1) {
        int n = __shfl_up_sync(0xFFFFFFFFu, sc, o);
        if (lane >= o) sc += n;
    }
    if (lane == 31) wsum[w] = sc;
    __syncthreads();
    if (w == 0) {
        int x = wsum[lane];
#pragma unroll
        for (int o = 1; o < 32; o <<= 1) {
            int n = __shfl_up_sync(0xFFFFFFFFu, x, o);
            if (lane >= o) x += n;
        }
        wsum[lane] = x;
    }
    __syncthreads();
    int excl = sc - tot + (w > 0 ? wsum[w - 1] : 0);
#pragma unroll
    for (int k = 0; k < 8; ++k) {
        int idx = t * 8 + k;
        int b = excl + v[k];
        base[idx] = b;
        fillp[idx] = b;
        dinv[idx] = rsqrtf((float)cnt[idx] + 1.0f);
    }
}
__global__ void fill_edges(const int* __restrict__ ei, int E, int* __restrict__ fillp,
                           int* __restrict__ esrc) {
    int e = blockIdx.x * blockDim.x + threadIdx.x;
    if (e >= E) return;
    int s = ei[e], d = ei[E + e];
    int pos = atomicAdd(&fillp[d], 1);
    esrc[pos] = s;
}
__launch_bounds__(256)
__global__ void gcn_gather(const float* __restrict__ xw, const float* __restrict__ dinv,
                           const int* __restrict__ base, const int* __restrict__ cnt,
                           const int* __restrict__ esrc, const float* __restrict__ gcn_b,
                           float* __restrict__ xl) {
    int node = blockIdx.x * 4 + (threadIdx.x >> 6);
    int c4 = (threadIdx.x & 63) * 4;
    float dd = dinv[node];
    float4 v0 = *(const float4*)&xw[(size_t)node * HH + c4];
    float ax = dd * v0.x, ay = dd * v0.y, az = dd * v0.z, aw = dd * v0.w;
    int b0 = __ldg(&base[node]);
    int n  = __ldg(&cnt[node]);
    int k = 0;
    for (; k + 4 <= n; k += 4) {
        int s0 = __ldg(&esrc[b0 + k]);
        int s1 = __ldg(&esrc[b0 + k + 1]);
        int s2 = __ldg(&esrc[b0 + k + 2]);
        int s3 = __ldg(&esrc[b0 + k + 3]);
        float w0 = __ldg(&dinv[s0]), w1 = __ldg(&dinv[s1]);
        float w2 = __ldg(&dinv[s2]), w3 = __ldg(&dinv[s3]);
        float4 a = *(const float4*)&xw[(size_t)s0 * HH + c4];
        float4 b = *(const float4*)&xw[(size_t)s1 * HH + c4];
        float4 c = *(const float4*)&xw[(size_t)s2 * HH + c4];
        float4 d = *(const float4*)&xw[(size_t)s3 * HH + c4];
        ax += w0 * a.x + w1 * b.x + w2 * c.x + w3 * d.x;
        ay += w0 * a.y + w1 * b.y + w2 * c.y + w3 * d.y;
        az += w0 * a.z + w1 * b.z + w2 * c.z + w3 * d.z;
        aw += w0 * a.w + w1 * b.w + w2 * c.w + w3 * d.w;
    }
    for (; k < n; ++k) {
        int s = __ldg(&esrc[b0 + k]);
        float ws = __ldg(&dinv[s]);
        float4 v = *(const float4*)&xw[(size_t)s * HH + c4];
        ax += ws * v.x; ay += ws * v.y; az += ws * v.z; aw += ws * v.w;
    }
    float4 bia = *(const float4*)&gcn_b[c4];
    float4 o;
    o.x = dd * ax + bia.x; o.y = dd * ay + bia.y;
    o.z = dd * az + bia.z; o.w = dd * aw + bia.w;
    *(float4*)&xl[(size_t)node * HH + c4] = o;
}

// ---------------- SPD: boolean matrix powers, warp-per-row ----------------
__launch_bounds__(256)
__global__ void spd_round(const uint32_t* __restrict__ adj, const uint32_t* __restrict__ Rp,
                          uint32_t* __restrict__ Rn) {
    int gw = (blockIdx.x * 256 + threadIdx.x) >> 5;
    int lane = threadIdx.x & 31;
    int g = gw >> 10, i = gw & 1023;
    const uint32_t* Rg = Rp + (size_t)g * MM * 32;
    uint32_t a = adj[((size_t)g * MM + i) * 32 + lane];
    uint32_t nw = Rg[i * 32 + lane];
    for (int w = 0; w < 32; ++w) {
        uint32_t f = __shfl_sync(0xFFFFFFFFu, a, w);
        while (f) {
            int b = __ffs((int)f) - 1;
            f &= f - 1;
            nw |= Rg[(w * 32 + b) * 32 + lane];
        }
    }
    Rn[((size_t)g * MM + i) * 32 + lane] = nw;
}
__device__ __forceinline__ uint32_t nibspread(uint32_t r, int q) {
    return (((r >> (q * 4)) & 0xFu) * 0x00204081u) & 0x01010101u;
}
__launch_bounds__(256)
__global__ void spd_final(const uint32_t* __restrict__ R1, const uint32_t* __restrict__ R2,
                          const uint32_t* __restrict__ R3, const uint32_t* __restrict__ R4,
                          const uint32_t* __restrict__ R5, unsigned char* __restrict__ dist) {
    int idx = blockIdx.x * 256 + threadIdx.x;
    int row = idx >> 5, w = idx & 31;
    uint32_t r1 = R1[idx], r2 = R2[idx], r3 = R3[idx], r4 = R4[idx], r5 = R5[idx];
    unsigned char* drow = dist + (size_t)row * MM;
    uint4* dp = (uint4*)(drow + w * 32);
    uint32_t o[8];
#pragma unroll
    for (int q = 0; q < 8; ++q) {
        uint32_t s = nibspread(r1, q) + nibspread(r2, q) + nibspread(r3, q)
                   + nibspread(r4, q) + nibspread(r5, q);
        o[q] = 0x06060606u - s;
    }
    dp[0] = make_uint4(o[0], o[1], o[2], o[3]);
    dp[1] = make_uint4(o[4], o[5], o[6], o[7]);
    int i = row & 1023;
    if ((i >> 5) == w) drow[i] = 0;
}

// ---------------- fp16 GEMM 128x128 (ldmatrix, fp16-accum + fp32 promote/32K) ----------------
template <int GELU, int RES, int OUTF16>
__launch_bounds__(256, 2)
__global__ void gemm_f16(const __half* __restrict__ Ag, const __half* __restrict__ Whg,
                         const float* __restrict__ bias, const float* __restrict__ res,
                         float* __restrict__ C, __half* __restrict__ Ch, int K, int F) {
    extern __shared__ unsigned char smp[];
    const int STG = 20480;
    int m0 = blockIdx.x * 128, f0 = blockIdx.y * 128;
    int tid = threadIdx.x, lane = tid & 31, warp = tid >> 5;
    int g = lane >> 2, tg = lane & 3;
    int wm = (warp >> 2) * 64, wn = (warp & 3) * 32;
    uint32_t smem_base = (uint32_t)__cvta_generic_to_shared(smp);

    uint32_t aOff = (uint32_t)(wm + (lane & 15)) * 80 + (uint32_t)(lane >> 4) * 16;
    uint32_t bOff = (uint32_t)(wn + ((lane >> 4) << 3) + (lane & 7)) * 80
                  + (uint32_t)((lane >> 3) & 1) * 16;

    float acc[4][4][4];
#pragma unroll
    for (int a = 0; a < 4; ++a)
#pragma unroll
        for (int b = 0; b < 4; ++b)
#pragma unroll
            for (int c = 0; c < 4; ++c) acc[a][b][c] = 0.f;

    auto load_stage = [&](int s, int k0) {
        uint32_t db = smem_base + s * STG;
        const __half* srcs[2] = { Ag + (size_t)m0 * K + k0, Whg + (size_t)f0 * K + k0 };
#pragma unroll
        for (int arr = 0; arr < 2; ++arr) {
            const __half* bp = srcs[arr];
            uint32_t ab = db + arr * 10240;
#pragma unroll
            for (int c = 0; c < 2; ++c) {
                int t = tid + c * 256;
                int row = t >> 2, ch = t & 3;
                CP16(ab + row * 80 + ch * 16, bp + (size_t)row * K + ch * 8);
            }
        }
        asm volatile("cp.async.commit_group;\n" ::);
    };

    int nk = K >> 5;
    load_stage(0, 0);
    for (int kc = 0; kc < nk; ++kc) {
        if (kc + 1 < nk) {
            load_stage((kc + 1) & 1, (kc + 1) << 5);
            asm volatile("cp.async.wait_group 1;\n" ::);
        } else {
            asm volatile("cp.async.wait_group 0;\n" ::);
        }
        __syncthreads();

        uint32_t stg = smem_base + (kc & 1) * STG;
        uint32_t aB  = stg + aOff;
        uint32_t whB = stg + 10240 + bOff;

        // load both ks fragments up front, chain fp16 accum over the 32-K chunk
        uint32_t b0[4][2], b1[4][2];
        LDSM4(b0[0][0], b0[0][1], b0[1][0], b0[1][1], whB);
        LDSM4(b0[2][0], b0[2][1], b0[3][0], b0[3][1], whB + 1280);
        LDSM4(b1[0][0], b1[0][1], b1[1][0], b1[1][1], whB + 32);
        LDSM4(b1[2][0], b1[2][1], b1[3][0], b1[3][1], whB + 1280 + 32);
#pragma unroll
        for (int mt = 0; mt < 4; ++mt) {
            uint32_t a00, a01, a02, a03, a10, a11, a12, a13;
            LDSM4(a00, a01, a02, a03, aB + mt * 1280);
            LDSM4(a10, a11, a12, a13, aB + mt * 1280 + 32);
#pragma unroll
            for (int nt = 0; nt < 4; ++nt) {
                uint32_t c0 = 0u, c1 = 0u;
                MMAH16(c0, c1, a00, a01, a02, a03, b0[nt][0], b0[nt][1]);
                MMAH16(c0, c1, a10, a11, a12, a13, b1[nt][0], b1[nt][1]);
                float2 f0v = __half22float2(*reinterpret_cast<__half2*>(&c0));
                float2 f1v = __half22float2(*reinterpret_cast<__half2*>(&c1));
                acc[mt][nt][0] += f0v.x;
                acc[mt][nt][1] += f0v.y;
                acc[mt][nt][2] += f1v.x;
                acc[mt][nt][3] += f1v.y;
            }
        }
        __syncthreads();
    }

#pragma unroll
    for (int mt = 0; mt < 4; ++mt) {
#pragma unroll
        for (int half = 0; half < 2; ++half) {
            int row = m0 + wm + mt * 16 + g + half * 8;
#pragma unroll
            for (int nt = 0; nt < 4; ++nt) {
                int col = f0 + wn + nt * 8 + tg * 2;
                float v0 = acc[mt][nt][half * 2 + 0];
                float v1 = acc[mt][nt][half * 2 + 1];
                if (bias) { v0 += bias[col]; v1 += bias[col + 1]; }
                if (GELU) { v0 = v0 * normcdff(v0); v1 = v1 * normcdff(v1); }
                if (RES)  { v0 += res[(size_t)row * F + col]; v1 += res[(size_t)row * F + col + 1]; }
                if (OUTF16) {
                    *(uint32_t*)(Ch + (size_t)row * F + col) = packh(v0, v1);
                } else {
                    float2 o; o.x = v0; o.y = v1;
                    *(float2*)(C + (size_t)row * F + col) = o;
                }
            }
        }
    }
}

// ---------------- qkv prepass ----------------
__launch_bounds__(256)
__global__ void qkv_prep(const float* __restrict__ qkv,
                         __half* __restrict__ qh, __half* __restrict__ kh,
                         __half* __restrict__ vth) {
    __shared__ float vsm[64][33];
    int nb = blockIdx.x * 64;
    int g = nb >> 10;
    int jb = nb & 1023;
    int tid = threadIdx.x;
    const float scale = 0.17677669529663687f;

#pragma unroll
    for (int it = 0; it < 32; ++it) {
        int flat = tid + it * 256;
        int row = flat >> 7, c4 = flat & 127;
        int node = nb + row;
        float4 v = *(const float4*)&qkv[(size_t)node * QKVD + c4 * 4];
        int c = c4 * 4;
        if (c < 256) {
            *(uint2*)(qh + (size_t)node * HH + c) =
                make_uint2(packh(v.x * scale, v.y * scale), packh(v.z * scale, v.w * scale));
        } else {
            *(uint2*)(kh + (size_t)node * HH + c - 256) =
                make_uint2(packh(v.x, v.y), packh(v.z, v.w));
        }
    }

    for (int h = 0; h < NHEADS; ++h) {
        __syncthreads();
#pragma unroll
        for (int it = 0; it < 2; ++it) {
            int flat = tid + it * 256;
            int row = flat >> 3, c4 = flat & 7;
            float4 v = *(const float4*)&qkv[(size_t)(nb + row) * QKVD + 512 + h * 32 + c4 * 4];
            vsm[row][c4 * 4 + 0] = v.x;
            vsm[row][c4 * 4 + 1] = v.y;
            vsm[row][c4 * 4 + 2] = v.z;
            vsm[row][c4 * 4 + 3] = v.w;
        }
        __syncthreads();
        int d = tid >> 3, j0 = (tid & 7) * 8;
        uint32_t hw[4];
#pragma unroll
        for (int p = 0; p < 4; ++p)
            hw[p] = packh(vsm[j0 + p * 2 + 0][d], vsm[j0 + p * 2 + 1][d]);
        size_t off = ((size_t)(g * NHEADS + h) * HDIM + d) * MM + jb + j0;
        *(uint4*)(vth + off) = make_uint4(hw[0], hw[1], hw[2], hw[3]);
    }
}

// ---------------- flash attention (fp16 single K/V, fp32 accum) ----------------
__launch_bounds__(256)
__global__ void attn_mma(const __half* __restrict__ qh, const __half* __restrict__ kh,
                         const __half* __restrict__ vth,
                         const unsigned char* __restrict__ dist, const float* __restrict__ bias_emb,
                         __half* __restrict__ oh) {
    extern __shared__ unsigned char smp[];
    const int STG = 18944;
    __shared__ float btab[8];
    int gh = blockIdx.x;
    int g = gh >> 3, h = gh & 7;
    int i0 = blockIdx.y * 128;
    int tid = threadIdx.x, lane = tid & 31, warp = tid >> 5;
    int r = lane >> 2, tg = lane & 3;
    if (tid < 7) btab[tid] = bias_emb[tid];
    uint32_t sb = (uint32_t)__cvta_generic_to_shared(smp);
    const float L2E = 1.44269504f;

    int rowA = i0 + warp * 16 + r;
    int rowB = rowA + 8;
    uint32_t qf[2][4];
#pragma unroll
    for (int kc = 0; kc < 2; ++kc) {
        size_t baseA = (size_t)(g * MM + rowA) * HH + h * HDIM + kc * 16 + tg * 2;
        size_t baseB = (size_t)(g * MM + rowB) * HH + h * HDIM + kc * 16 + tg * 2;
        qf[kc][0] = *(const uint32_t*)(qh + baseA);
        qf[kc][1] = *(const uint32_t*)(qh + baseB);
        qf[kc][2] = *(const uint32_t*)(qh + baseA + 8);
        qf[kc][3] = *(const uint32_t*)(qh + baseB + 8);
    }

    float acc_o[4][4];
#pragma unroll
    for (int a = 0; a < 4; ++a)
#pragma unroll
        for (int b = 0; b < 4; ++b) acc_o[a][b] = 0.f;
    float mA = -1e30f, mB = -1e30f, lA = 0.f, lB = 0.f;

    const unsigned char* drowA = dist + ((size_t)(g * MM + rowA)) * MM;
    const unsigned char* drowB = dist + ((size_t)(g * MM + rowB)) * MM;

    auto load_stage = [&](int s, int j0) {
        uint32_t db = sb + s * STG;
#pragma unroll
        for (int c = 0; c < 2; ++c) {
            int t = tid + c * 256;
            int row = t >> 2, ch = t & 3;
            const __half* src = kh + (size_t)(g * MM + j0 + row) * HH + h * HDIM + ch * 8;
            CP16(db + row * 80 + ch * 16, src);
        }
#pragma unroll
        for (int c = 0; c < 2; ++c) {
            int t = tid + c * 256;
            int row = t >> 4, ch = t & 15;
            size_t off = ((size_t)(gh) * HDIM + row) * MM + j0 + ch * 8;
            CP16(db + 10240 + row * 272 + ch * 16, vth + off);
        }
        asm volatile("cp.async.commit_group;\n" ::);
    };

    load_stage(0, 0);
    for (int ch = 0; ch < 8; ++ch) {
        int j0 = ch * 128;
        if (ch < 7) {
            load_stage((ch + 1) & 1, j0 + 128);
            asm volatile("cp.async.wait_group 1;\n" ::);
        } else {
            asm volatile("cp.async.wait_group 0;\n" ::);
        }
        __syncthreads();

        const uint32_t* KH = (const uint32_t*)(smp + (ch & 1) * STG);
        const uint32_t* VH = KH + 2560;

        float acc_s[16][4];
#pragma unroll
        for (int nt = 0; nt < 16; ++nt)
#pragma unroll
            for (int c = 0; c < 4; ++c) acc_s[nt][c] = 0.f;
#pragma unroll
        for (int kc = 0; kc < 2; ++kc) {
#pragma unroll
            for (int nt = 0; nt < 16; ++nt) {
                int idx = (nt * 8 + r) * 20 + kc * 8 + tg;
                MMAH(acc_s[nt], qf[kc][0], qf[kc][1], qf[kc][2], qf[kc][3],
                     KH[idx], KH[idx + 4]);
            }
        }

        float cmA = -1e30f, cmB = -1e30f;
#pragma unroll
        for (int nt = 0; nt < 16; ++nt) {
            uchar2 dA = *(const uchar2*)(drowA + j0 + nt * 8 + tg * 2);
            uchar2 dB = *(const uchar2*)(drowB + j0 + nt * 8 + tg * 2);
            acc_s[nt][0] += btab[dA.x];
            acc_s[nt][1] += btab[dA.y];
            acc_s[nt][2] += btab[dB.x];
            acc_s[nt][3] += btab[dB.y];
            cmA = fmaxf(cmA, fmaxf(acc_s[nt][0], acc_s[nt][1]));
            cmB = fmaxf(cmB, fmaxf(acc_s[nt][2], acc_s[nt][3]));
        }
        cmA = fmaxf(cmA, __shfl_xor_sync(0xFFFFFFFFu, cmA, 1));
        cmA = fmaxf(cmA, __shfl_xor_sync(0xFFFFFFFFu, cmA, 2));
        cmB = fmaxf(cmB, __shfl_xor_sync(0xFFFFFFFFu, cmB, 1));
        cmB = fmaxf(cmB, __shfl_xor_sync(0xFFFFFFFFu, cmB, 2));

        float mAn = fmaxf(mA, cmA), mBn = fmaxf(mB, cmB);
        float corrA = ex2f((mA - mAn) * L2E);
        float corrB = ex2f((mB - mBn) * L2E);
        mA = mAn; mB = mBn;

        uint32_t ph0[16], ph1[16];
        float lsA = 0.f, lsB = 0.f;
#pragma unroll
        for (int nt = 0; nt < 16; ++nt) {
            float p0 = ex2f((acc_s[nt][0] - mA) * L2E);
            float p1 = ex2f((acc_s[nt][1] - mA) * L2E);
            float p2 = ex2f((acc_s[nt][2] - mB) * L2E);
            float p3 = ex2f((acc_s[nt][3] - mB) * L2E);
            lsA += p0 + p1; lsB += p2 + p3;
            ph0[nt] = packh(p0, p1);
            ph1[nt] = packh(p2, p3);
        }
        lsA += __shfl_xor_sync(0xFFFFFFFFu, lsA, 1);
        lsA += __shfl_xor_sync(0xFFFFFFFFu, lsA, 2);
        lsB += __shfl_xor_sync(0xFFFFFFFFu, lsB, 1);
        lsB += __shfl_xor_sync(0xFFFFFFFFu, lsB, 2);
        lA = lA * corrA + lsA;
        lB = lB * corrB + lsB;

#pragma unroll
        for (int nto = 0; nto < 4; ++nto) {
            acc_o[nto][0] *= corrA; acc_o[nto][1] *= corrA;
            acc_o[nto][2] *= corrB; acc_o[nto][3] *= corrB;
        }

#pragma unroll
        for (int kc = 0; kc < 8; ++kc) {
            uint32_t a0 = ph0[2 * kc], a1 = ph1[2 * kc], a2 = ph0[2 * kc + 1], a3 = ph1[2 * kc + 1];
#pragma unroll
            for (int nto = 0; nto < 4; ++nto) {
                int idx = (nto * 8 + r) * 68 + kc * 8 + tg;
                MMAH(acc_o[nto], a0, a1, a2, a3, VH[idx], VH[idx + 4]);
            }
        }
        __syncthreads();
    }

    float invA = 1.f / lA, invB = 1.f / lB;
#pragma unroll
    for (int nto = 0; nto < 4; ++nto) {
        int col = h * HDIM + nto * 8 + tg * 2;
        *(uint32_t*)(oh + (size_t)(g * MM + rowA) * HH + col) =
            packh(acc_o[nto][0] * invA, acc_o[nto][1] * invA);
        *(uint32_t*)(oh + (size_t)(g * MM + rowB) * HH + col) =
            packh(acc_o[nto][2] * invB, acc_o[nto][3] * invB);
    }
}

// ---------------- LayerNorm: warp-per-row, 8 rows per CTA ----------------
__launch_bounds__(256)
__global__ void ln_kernel(const float* __restrict__ a, const float* __restrict__ b,
                          const float* __restrict__ c, const float* __restrict__ gam,
                          const float* __restrict__ bet, float* __restrict__ out,
                          __half* __restrict__ oh) {
    int row = blockIdx.x * 8 + (threadIdx.x >> 5);
    int lane = threadIdx.x & 31;
    size_t idx = (size_t)row * HH + lane * 8;
    float v[8];
    float4 u0 = *(const float4*)&a[idx];
    float4 u1 = *(const float4*)&a[idx + 4];
    v[0] = u0.x; v[1] = u0.y; v[2] = u0.z; v[3] = u0.w;
    v[4] = u1.x; v[5] = u1.y; v[6] = u1.z; v[7] = u1.w;
    if (b) {
        float4 b0 = *(const float4*)&b[idx];
        float4 b1 = *(const float4*)&b[idx + 4];
        v[0] += b0.x; v[1] += b0.y; v[2] += b0.z; v[3] += b0.w;
        v[4] += b1.x; v[5] += b1.y; v[6] += b1.z; v[7] += b1.w;
    }
    if (c) {
        float4 c0 = *(const float4*)&c[idx];
        float4 c1 = *(const float4*)&c[idx + 4];
        v[0] += c0.x; v[1] += c0.y; v[2] += c0.z; v[3] += c0.w;
        v[4] += c1.x; v[5] += c1.y; v[6] += c1.z; v[7] += c1.w;
    }
    float s = 0.f, s2 = 0.f;
#pragma unroll
    for (int j = 0; j < 8; ++j) { s += v[j]; s2 += v[j] * v[j]; }
#pragma unroll
    for (int o = 16; o; o >>= 1) {
        s  += __shfl_xor_sync(0xFFFFFFFFu, s, o);
        s2 += __shfl_xor_sync(0xFFFFFFFFu, s2, o);
    }
    float mean = s * (1.f / HH);
    float var  = s2 * (1.f / HH) - mean * mean;
    float rstd = rsqrtf(var + 1e-5f);
    int gcol = lane * 8;
    float4 g0 = *(const float4*)&gam[gcol];
    float4 g1 = *(const float4*)&gam[gcol + 4];
    float4 e0 = *(const float4*)&bet[gcol];
    float4 e1 = *(const float4*)&bet[gcol + 4];
    float r[8];
    r[0] = (v[0] - mean) * rstd * g0.x + e0.x;
    r[1] = (v[1] - mean) * rstd * g0.y + e0.y;
    r[2] = (v[2] - mean) * rstd * g0.z + e0.z;
    r[3] = (v[3] - mean) * rstd * g0.w + e0.w;
    r[4] = (v[4] - mean) * rstd * g1.x + e1.x;
    r[5] = (v[5] - mean) * rstd * g1.y + e1.y;
    r[6] = (v[6] - mean) * rstd * g1.z + e1.z;
    r[7] = (v[7] - mean) * rstd * g1.w + e1.w;
    float4 o0, o1;
    o0.x = r[0]; o0.y = r[1]; o0.z = r[2]; o0.w = r[3];
    o1.x = r[4]; o1.y = r[5]; o1.z = r[6]; o1.w = r[7];
    *(float4*)&out[idx] = o0;
    *(float4*)&out[idx + 4] = o1;
    if (oh) {
        *(uint4*)(oh + idx) = make_uint4(packh(r[0], r[1]), packh(r[2], r[3]),
                                         packh(r[4], r[5]), packh(r[6], r[7]));
    }
}

// ---------------- host ----------------
static void* sym(const void* s) { void* p = nullptr; cudaGetSymbolAddress(&p, s); return p; }

static cudaStream_t s_s1, s_s2;
static cudaEvent_t  s_evA, s_evXW, s_evSPD, s_evGA;
static struct StreamInit {
    StreamInit() {
        cudaStreamCreateWithFlags(&s_s1, cudaStreamNonBlocking);
        cudaStreamCreateWithFlags(&s_s2, cudaStreamNonBlocking);
        cudaEventCreateWithFlags(&s_evA,   cudaEventDisableTiming);
        cudaEventCreateWithFlags(&s_evXW,  cudaEventDisableTiming);
        cudaEventCreateWithFlags(&s_evSPD, cudaEventDisableTiming);
        cudaEventCreateWithFlags(&s_evGA,  cudaEventDisableTiming);
    }
} s_streamInit;

extern "C" void kernel_launch(void* const* d_in, const int* in_sizes, int n_in,
                              void* d_out, int out_size) {
    const float* x      = (const float*)d_in[0];
    const float* gcn_w  = (const float*)d_in[1];
    const float* gcn_b  = (const float*)d_in[2];
    const float* qkv_w  = (const float*)d_in[3];
    const float* qkv_b  = (const float*)d_in[4];
    const float* proj_w = (const float*)d_in[5];
    const float* proj_b = (const float*)d_in[6];
    const float* ln1_g  = (const float*)d_in[7];
    const float* ln1_b  = (const float*)d_in[8];
    const float* ln2_g  = (const float*)d_in[9];
    const float* ln2_b  = (const float*)d_in[10];
    const float* ffn1_w = (const float*)d_in[11];
    const float* ffn1_b = (const float*)d_in[12];
    const float* ffn2_w = (const float*)d_in[13];
    const float* ffn2_b = (const float*)d_in[14];
    const float* bias_e = (const float*)d_in[15];
    const float* oln1_g = (const float*)d_in[16];
    const float* oln1_b = (const float*)d_in[17];
    const float* oln2_g = (const float*)d_in[18];
    const float* oln2_b = (const float*)d_in[19];
    const float* offn1_w= (const float*)d_in[20];
    const float* offn1_b= (const float*)d_in[21];
    const float* offn2_w= (const float*)d_in[22];
    const float* offn2_b= (const float*)d_in[23];
    const int*   ei     = (const int*)d_in[24];
    int E = in_sizes[24] / 2;

    float*    p_dinv = (float*)sym(g_dinv);
    float*    p_xw   = (float*)sym(g_xw);
    float*    p_xl   = (float*)sym(g_xl);
    uint32_t* p_adj  = (uint32_t*)sym(g_adj);
    uint32_t* p_R2   = (uint32_t*)sym(g_R2);
    uint32_t* p_R3   = (uint32_t*)sym(g_R3);
    uint32_t* p_R4   = (uint32_t*)sym(g_R4);
    uint32_t* p_R5   = (uint32_t*)sym(g_R5);
    unsigned char* p_dist = (unsigned char*)sym(g_dist);
    float*    p_qkv  = (float*)sym(g_qkv);
    float*    p_tmp  = (float*)sym(g_tmp);
    float*    p_h1   = (float*)sym(g_h1);
    float*    p_h2   = (float*)sym(g_h2);
    float*    p_y    = (float*)sym(g_y);
    int*      p_cnt  = (int*)sym(g_cnt);
    int*      p_base = (int*)sym(g_base);
    int*      p_fill = (int*)sym(g_fillp);
    int*      p_esrc = (int*)sym(g_esrc);
    __half* x_h   = (__half*)sym(g_x_h);
    __half* at_h  = (__half*)sym(g_at_h);
    __half* h1_h  = (__half*)sym(g_h1_h);
    __half* y_h   = (__half*)sym(g_y_h);
    __half* mid_h = (__half*)sym(g_mid_h);
    __half* q_h   = (__half*)sym(g_q_h);
    __half* k_h   = (__half*)sym(g_k_h);
    __half* vt_h  = (__half*)sym(g_vt_h);
    __half* whi   = (__half*)sym(g_whi);
    float* out = (float*)d_out;

    const int SMEM  = 40960;
    const int ASMEM = 37888;
    cudaFuncSetAttribute(gemm_f16<0,0,0>, cudaFuncAttributeMaxDynamicSharedMemorySize, SMEM);
    cudaFuncSetAttribute(gemm_f16<0,1,0>, cudaFuncAttributeMaxDynamicSharedMemorySize, SMEM);
    cudaFuncSetAttribute(gemm_f16<1,0,1>, cudaFuncAttributeMaxDynamicSharedMemorySize, SMEM);
    cudaFuncSetAttribute(attn_mma, cudaFuncAttributeMaxDynamicSharedMemorySize, ASMEM);

    // --- default stream: counts + adjacency, then fork ---
    zero_prep<<<(GG * MM * 32 + 255) / 256, 256>>>(p_cnt, p_adj);
    edge_prep<<<(E + 255) / 256, 256>>>(ei, E, p_cnt, p_adj);
    cudaEventRecord(s_evA, 0);

    // --- s1: SPD chain ---
    cudaStreamWaitEvent(s_s1, s_evA, 0);
    spd_round<<<NN * 32 / 256, 256, 0, s_s1>>>(p_adj, p_adj, p_R2);
    spd_round<<<NN * 32 / 256, 256, 0, s_s1>>>(p_adj, p_R2, p_R3);
    spd_round<<<NN * 32 / 256, 256, 0, s_s1>>>(p_adj, p_R3, p_R4);
    spd_round<<<NN * 32 / 256, 256, 0, s_s1>>>(p_adj, p_R4, p_R5);
    spd_final<<<NN * 32 / 256, 256, 0, s_s1>>>(p_adj, p_R2, p_R3, p_R4, p_R5, p_dist);
    cudaEventRecord(s_evSPD, s_s1);

    // --- s2: edge CSR + GCN gather ---
    cudaStreamWaitEvent(s_s2, s_evA, 0);
    scan_kernel<<<1, 1024, 0, s_s2>>>(p_cnt, p_base, p_fill, p_dinv);
    fill_edges<<<(E + 255) / 256, 256, 0, s_s2>>>(ei, E, p_fill, p_esrc);

    // --- default stream: splits + GEMM chain ---
    splitw<<<(344064 + 255) / 256, 256>>>((const float4*)gcn_w, (const float4*)qkv_w,
        (const float4*)proj_w, (const float4*)ffn1_w, (const float4*)ffn2_w,
        (const float4*)offn1_w, (const float4*)offn2_w, whi);
    splitx<<<(NN * HH / 4 + 255) / 256, 256>>>((const float4*)x, x_h, NN * HH / 4);
    gemm_f16<0,0,0><<<dim3(NN/128, HH/128), 256, SMEM>>>(x_h, whi + OFF_GCN,
        nullptr, nullptr, p_xw, nullptr, HH, HH);
    cudaEventRecord(s_evXW, 0);
    cudaStreamWaitEvent(s_s2, s_evXW, 0);
    gcn_gather<<<NN / 4, 256, 0, s_s2>>>(p_xw, p_dinv, p_base, p_cnt, p_esrc, gcn_b, p_xl);
    cudaEventRecord(s_evGA, s_s2);

    gemm_f16<0,0,0><<<dim3(NN/128, QKVD/128), 256, SMEM>>>(x_h, whi + OFF_QKV,
        qkv_b, nullptr, p_qkv, nullptr, HH, QKVD);
    qkv_prep<<<NN / 64, 256>>>(p_qkv, q_h, k_h, vt_h);

    cudaStreamWaitEvent(0, s_evSPD, 0);
    attn_mma<<<dim3(GG * NHEADS, MM / 128), 256, ASMEM>>>(q_h, k_h, vt_h, p_dist, bias_e, at_h);
    gemm_f16<0,1,0><<<dim3(NN/128, HH/128), 256, SMEM>>>(at_h, whi + OFF_PROJ,
        proj_b, x, p_tmp, nullptr, HH, HH);
    ln_kernel<<<NN / 8, 256>>>(p_tmp, nullptr, nullptr, ln1_g, ln1_b, p_h1, h1_h);
    gemm_f16<1,0,1><<<dim3(NN/128, FFND/128), 256, SMEM>>>(h1_h, whi + OFF_FFN1,
        ffn1_b, nullptr, nullptr, mid_h, HH, FFND);
    gemm_f16<0,1,0><<<dim3(NN/128, HH/128), 256, SMEM>>>(mid_h, whi + OFF_FFN2,
        ffn2_b, p_h1, p_tmp, nullptr, FFND, HH);
    ln_kernel<<<NN / 8, 256>>>(p_tmp, nullptr, nullptr, ln2_g, ln2_b, p_h2, nullptr);

    // --- GPS combine + outer FFN ---
    cudaStreamWaitEvent(0, s_evGA, 0);
    ln_kernel<<<NN / 8, 256>>>(x, p_xl, p_h2, oln1_g, oln1_b, p_y, y_h);
    gemm_f16<1,0,1><<<dim3(NN/128, FFND/128), 256, SMEM>>>(y_h, whi + OFF_OFFN1,
        offn1_b, nullptr, nullptr, mid_h, HH, FFND);
    gemm_f16<0,1,0><<<dim3(NN/128, HH/128), 256, SMEM>>>(mid_h, whi + OFF_OFFN2,
        offn2_b, p_y, p_tmp, nullptr, FFND, HH);
    ln_kernel<<<NN / 8, 256>>>(p_tmp, nullptr, nullptr, oln2_g, oln2_b, out, nullptr);
}

// round 15
// speedup vs baseline: 1.0656x; 1.0656x over previous
#include <cuda_runtime.h>
#include <cuda_fp16.h>
#include <cstdint>
#include <math.h>

#define GG 8
#define MM 1024
#define NN 8192
#define HH 256
#define NHEADS 8
#define HDIM 32
#define FFND 1024
#define QKVD 768

// ---------------- scratch ----------------
__device__ float    g_dinv[NN];
__device__ float    g_xw  [NN * HH];
__device__ float    g_xl  [NN * HH];
__device__ uint32_t g_adj [GG * MM * 32];
__device__ uint32_t g_R2  [GG * MM * 32];
__device__ uint32_t g_R3  [GG * MM * 32];
__device__ uint32_t g_R4  [GG * MM * 32];
__device__ uint32_t g_R5  [GG * MM * 32];
__device__ unsigned char g_dist[(size_t)GG * MM * MM];
__device__ float    g_qkv [(size_t)NN * QKVD];
__device__ float    g_tmp [NN * HH];
__device__ float    g_h1  [NN * HH];
__device__ float    g_y   [NN * HH];
__device__ int      g_cnt [NN];
__device__ int      g_base[NN];
__device__ int      g_fillp[NN];
__device__ int      g_esrc[262144];

#define AL16 __align__(16)
__device__ AL16 __half g_x_h [NN * HH];
__device__ AL16 __half g_at_h[NN * HH];
__device__ AL16 __half g_h1_h[NN * HH];
__device__ AL16 __half g_y_h [NN * HH];
__device__ AL16 __half g_mid_h[(size_t)NN * FFND];
__device__ AL16 __half g_q_h [NN * HH];
__device__ AL16 __half g_k_h [NN * HH];
__device__ AL16 __half g_vt_h[GG * NHEADS * HDIM * MM];
__device__ AL16 __half g_whi[1376256];
#define OFF_GCN   0
#define OFF_QKV   65536
#define OFF_PROJ  262144
#define OFF_FFN1  327680
#define OFF_FFN2  589824
#define OFF_OFFN1 851968
#define OFF_OFFN2 1114112

// ---------------- helpers ----------------
__device__ __forceinline__ uint32_t packh(float a, float b) {
    uint32_t r;
    asm("cvt.rn.f16x2.f32 %0, %1, %2;" : "=r"(r) : "f"(b), "f"(a));
    return r;
}
__device__ __forceinline__ float ex2f(float x) {
    float y; asm("ex2.approx.f32 %0, %1;" : "=f"(y) : "f"(x)); return y;
}
#define CP16(dst, src) asm volatile("cp.async.cg.shared.global [%0], [%1], 16;\n" :: "r"(dst), "l"(src))
#define MMAH(d, a0, a1, a2, a3, b0, b1) \
    asm volatile("mma.sync.aligned.m16n8k16.row.col.f32.f16.f16.f32 " \
                 "{%0,%1,%2,%3}, {%4,%5,%6,%7}, {%8,%9}, {%0,%1,%2,%3};" \
                 : "+f"(d[0]), "+f"(d[1]), "+f"(d[2]), "+f"(d[3]) \
                 : "r"(a0), "r"(a1), "r"(a2), "r"(a3), "r"(b0), "r"(b1))
#define LDSM4(r0, r1, r2, r3, addr) \
    asm volatile("ldmatrix.sync.aligned.m8n8.x4.shared.b16 {%0,%1,%2,%3}, [%4];" \
                 : "=r"(r0), "=r"(r1), "=r"(r2), "=r"(r3) : "r"(addr))

// ---------------- splits (plain fp16 cast) ----------------
__global__ void splitx(const float4* __restrict__ in, __half* __restrict__ hi, int n4) {
    int i = blockIdx.x * blockDim.x + threadIdx.x;
    if (i >= n4) return;
    float4 v = in[i];
    *(uint2*)(hi + i * 4) = make_uint2(packh(v.x, v.y), packh(v.z, v.w));
}
__global__ void splitw(const float4* w0, const float4* w1, const float4* w2, const float4* w3,
                       const float4* w4, const float4* w5, const float4* w6,
                       __half* __restrict__ hi) {
    int i = blockIdx.x * blockDim.x + threadIdx.x;
    if (i >= 344064) return;
    const float4* src; int base;
    if      (i < 16384)  { src = w0; base = 0; }
    else if (i < 65536)  { src = w1; base = 16384; }
    else if (i < 81920)  { src = w2; base = 65536; }
    else if (i < 147456) { src = w3; base = 81920; }
    else if (i < 212992) { src = w4; base = 147456; }
    else if (i < 278528) { src = w5; base = 212992; }
    else                 { src = w6; base = 278528; }
    float4 v = src[i - base];
    *(uint2*)(hi + (size_t)i * 4) = make_uint2(packh(v.x, v.y), packh(v.z, v.w));
}

// ---------------- graph prep ----------------
__global__ void zero_prep(int* __restrict__ cnt, uint32_t* __restrict__ adj) {
    int i = blockIdx.x * blockDim.x + threadIdx.x;
    if (i < GG * MM * 32) adj[i] = 0u;
    if (i < NN) cnt[i] = 0;
}
__global__ void edge_prep(const int* __restrict__ ei, int E, int* __restrict__ cnt,
                          uint32_t* __restrict__ adj) {
    int e = blockIdx.x * blockDim.x + threadIdx.x;
    if (e >= E) return;
    int s = ei[e], d = ei[E + e];
    atomicAdd(&cnt[d], 1);
    if (s == d || (s >> 10) != (d >> 10)) return;
    int g = s >> 10, ls = s & 1023, ld = d & 1023;
    atomicOr(&adj[((size_t)g * MM + ls) * 32 + (ld >> 5)], 1u << (ld & 31));
    atomicOr(&adj[((size_t)g * MM + ld) * 32 + (ls >> 5)], 1u << (ls & 31));
}
__global__ void scan_kernel(const int* __restrict__ cnt, int* __restrict__ base,
                            int* __restrict__ fillp, float* __restrict__ dinv) {
    __shared__ int wsum[32];
    int t = threadIdx.x;
    int v[8]; int s = 0;
#pragma unroll
    for (int k = 0; k < 8; ++k) { v[k] = s; s += cnt[t * 8 + k]; }
    int lane = t & 31, w = t >> 5;
    int tot = s, sc = s;
#pragma unroll
    for (int o = 1; o < 32; o <<= 1) {
        int n = __shfl_up_sync(0xFFFFFFFFu, sc, o);
        if (lane >= o) sc += n;
    }
    if (lane == 31) wsum[w] = sc;
    __syncthreads();
    if (w == 0) {
        int x = wsum[lane];
#pragma unroll
        for (int o = 1; o < 32; o <<= 1) {
            int n = __shfl_up_sync(0xFFFFFFFFu, x, o);
            if (lane >= o) x += n;
        }
        wsum[lane] = x;
    }
    __syncthreads();
    int excl = sc - tot + (w > 0 ? wsum[w - 1] : 0);
#pragma unroll
    for (int k = 0; k < 8; ++k) {
        int idx = t * 8 + k;
        int b = excl + v[k];
        base[idx] = b;
        fillp[idx] = b;
        dinv[idx] = rsqrtf((float)cnt[idx] + 1.0f);
    }
}
__global__ void fill_edges(const int* __restrict__ ei, int E, int* __restrict__ fillp,
                           int* __restrict__ esrc) {
    int e = blockIdx.x * blockDim.x + threadIdx.x;
    if (e >= E) return;
    int s = ei[e], d = ei[E + e];
    int pos = atomicAdd(&fillp[d], 1);
    esrc[pos] = s;
}
__launch_bounds__(256)
__global__ void gcn_gather(const float* __restrict__ xw, const float* __restrict__ dinv,
                           const int* __restrict__ base, const int* __restrict__ cnt,
                           const int* __restrict__ esrc, const float* __restrict__ gcn_b,
                           float* __restrict__ xl) {
    int node = blockIdx.x * 4 + (threadIdx.x >> 6);
    int c4 = (threadIdx.x & 63) * 4;
    float dd = dinv[node];
    float4 v0 = *(const float4*)&xw[(size_t)node * HH + c4];
    float ax = dd * v0.x, ay = dd * v0.y, az = dd * v0.z, aw = dd * v0.w;
    int b0 = __ldg(&base[node]);
    int n  = __ldg(&cnt[node]);
    int k = 0;
    for (; k + 4 <= n; k += 4) {
        int s0 = __ldg(&esrc[b0 + k]);
        int s1 = __ldg(&esrc[b0 + k + 1]);
        int s2 = __ldg(&esrc[b0 + k + 2]);
        int s3 = __ldg(&esrc[b0 + k + 3]);
        float w0 = __ldg(&dinv[s0]), w1 = __ldg(&dinv[s1]);
        float w2 = __ldg(&dinv[s2]), w3 = __ldg(&dinv[s3]);
        float4 a = *(const float4*)&xw[(size_t)s0 * HH + c4];
        float4 b = *(const float4*)&xw[(size_t)s1 * HH + c4];
        float4 c = *(const float4*)&xw[(size_t)s2 * HH + c4];
        float4 d = *(const float4*)&xw[(size_t)s3 * HH + c4];
        ax += w0 * a.x + w1 * b.x + w2 * c.x + w3 * d.x;
        ay += w0 * a.y + w1 * b.y + w2 * c.y + w3 * d.y;
        az += w0 * a.z + w1 * b.z + w2 * c.z + w3 * d.z;
        aw += w0 * a.w + w1 * b.w + w2 * c.w + w3 * d.w;
    }
    for (; k < n; ++k) {
        int s = __ldg(&esrc[b0 + k]);
        float ws = __ldg(&dinv[s]);
        float4 v = *(const float4*)&xw[(size_t)s * HH + c4];
        ax += ws * v.x; ay += ws * v.y; az += ws * v.z; aw += ws * v.w;
    }
    float4 bia = *(const float4*)&gcn_b[c4];
    float4 o;
    o.x = dd * ax + bia.x; o.y = dd * ay + bia.y;
    o.z = dd * az + bia.z; o.w = dd * aw + bia.w;
    *(float4*)&xl[(size_t)node * HH + c4] = o;
}

// ---------------- SPD: boolean matrix powers, warp-per-row ----------------
__launch_bounds__(256)
__global__ void spd_round(const uint32_t* __restrict__ adj, const uint32_t* __restrict__ Rp,
                          uint32_t* __restrict__ Rn) {
    int gw = (blockIdx.x * 256 + threadIdx.x) >> 5;
    int lane = threadIdx.x & 31;
    int g = gw >> 10, i = gw & 1023;
    const uint32_t* Rg = Rp + (size_t)g * MM * 32;
    uint32_t a = adj[((size_t)g * MM + i) * 32 + lane];
    uint32_t nw = Rg[i * 32 + lane];
    for (int w = 0; w < 32; ++w) {
        uint32_t f = __shfl_sync(0xFFFFFFFFu, a, w);
        while (f) {
            int b = __ffs((int)f) - 1;
            f &= f - 1;
            nw |= Rg[(w * 32 + b) * 32 + lane];
        }
    }
    Rn[((size_t)g * MM + i) * 32 + lane] = nw;
}
__device__ __forceinline__ uint32_t nibspread(uint32_t r, int q) {
    return (((r >> (q * 4)) & 0xFu) * 0x00204081u) & 0x01010101u;
}
__launch_bounds__(256)
__global__ void spd_final(const uint32_t* __restrict__ R1, const uint32_t* __restrict__ R2,
                          const uint32_t* __restrict__ R3, const uint32_t* __restrict__ R4,
                          const uint32_t* __restrict__ R5, unsigned char* __restrict__ dist) {
    int idx = blockIdx.x * 256 + threadIdx.x;
    int row = idx >> 5, w = idx & 31;
    uint32_t r1 = R1[idx], r2 = R2[idx], r3 = R3[idx], r4 = R4[idx], r5 = R5[idx];
    unsigned char* drow = dist + (size_t)row * MM;
    uint4* dp = (uint4*)(drow + w * 32);
    uint32_t o[8];
#pragma unroll
    for (int q = 0; q < 8; ++q) {
        uint32_t s = nibspread(r1, q) + nibspread(r2, q) + nibspread(r3, q)
                   + nibspread(r4, q) + nibspread(r5, q);
        o[q] = 0x06060606u - s;
    }
    dp[0] = make_uint4(o[0], o[1], o[2], o[3]);
    dp[1] = make_uint4(o[4], o[5], o[6], o[7]);
    int i = row & 1023;
    if ((i >> 5) == w) drow[i] = 0;
}

// ---------------- fp16 GEMM 128x128 (ldmatrix, fp32 accum) ----------------
template <int GELU, int RES, int OUTF16>
__launch_bounds__(256, 2)
__global__ void gemm_f16(const __half* __restrict__ Ag, const __half* __restrict__ Whg,
                         const float* __restrict__ bias, const float* __restrict__ res,
                         float* __restrict__ C, __half* __restrict__ Ch, int K, int F) {
    extern __shared__ unsigned char smp[];
    const int STG = 20480;
    int m0 = blockIdx.x * 128, f0 = blockIdx.y * 128;
    int tid = threadIdx.x, lane = tid & 31, warp = tid >> 5;
    int g = lane >> 2, tg = lane & 3;
    int wm = (warp >> 2) * 64, wn = (warp & 3) * 32;
    uint32_t smem_base = (uint32_t)__cvta_generic_to_shared(smp);

    uint32_t aOff = (uint32_t)(wm + (lane & 15)) * 80 + (uint32_t)(lane >> 4) * 16;
    uint32_t bOff = (uint32_t)(wn + ((lane >> 4) << 3) + (lane & 7)) * 80
                  + (uint32_t)((lane >> 3) & 1) * 16;

    float acc[4][4][4];
#pragma unroll
    for (int a = 0; a < 4; ++a)
#pragma unroll
        for (int b = 0; b < 4; ++b)
#pragma unroll
            for (int c = 0; c < 4; ++c) acc[a][b][c] = 0.f;

    auto load_stage = [&](int s, int k0) {
        uint32_t db = smem_base + s * STG;
        const __half* srcs[2] = { Ag + (size_t)m0 * K + k0, Whg + (size_t)f0 * K + k0 };
#pragma unroll
        for (int arr = 0; arr < 2; ++arr) {
            const __half* bp = srcs[arr];
            uint32_t ab = db + arr * 10240;
#pragma unroll
            for (int c = 0; c < 2; ++c) {
                int t = tid + c * 256;
                int row = t >> 2, ch = t & 3;
                CP16(ab + row * 80 + ch * 16, bp + (size_t)row * K + ch * 8);
            }
        }
        asm volatile("cp.async.commit_group;\n" ::);
    };

    int nk = K >> 5;
    load_stage(0, 0);
    for (int kc = 0; kc < nk; ++kc) {
        if (kc + 1 < nk) {
            load_stage((kc + 1) & 1, (kc + 1) << 5);
            asm volatile("cp.async.wait_group 1;\n" ::);
        } else {
            asm volatile("cp.async.wait_group 0;\n" ::);
        }
        __syncthreads();

        uint32_t stg = smem_base + (kc & 1) * STG;
        uint32_t aB  = stg + aOff;
        uint32_t whB = stg + 10240 + bOff;
#pragma unroll
        for (int ks = 0; ks < 2; ++ks) {
            uint32_t bh[4][2];
            LDSM4(bh[0][0], bh[0][1], bh[1][0], bh[1][1], whB + ks * 32);
            LDSM4(bh[2][0], bh[2][1], bh[3][0], bh[3][1], whB + 1280 + ks * 32);
#pragma unroll
            for (int mt = 0; mt < 4; ++mt) {
                uint32_t a0, a1, a2, a3;
                LDSM4(a0, a1, a2, a3, aB + mt * 1280 + ks * 32);
#pragma unroll
                for (int nt = 0; nt < 4; ++nt)
                    MMAH(acc[mt][nt], a0, a1, a2, a3, bh[nt][0], bh[nt][1]);
            }
        }
        __syncthreads();
    }

#pragma unroll
    for (int mt = 0; mt < 4; ++mt) {
#pragma unroll
        for (int half = 0; half < 2; ++half) {
            int row = m0 + wm + mt * 16 + g + half * 8;
#pragma unroll
            for (int nt = 0; nt < 4; ++nt) {
                int col = f0 + wn + nt * 8 + tg * 2;
                float v0 = acc[mt][nt][half * 2 + 0];
                float v1 = acc[mt][nt][half * 2 + 1];
                if (bias) { v0 += bias[col]; v1 += bias[col + 1]; }
                if (GELU) { v0 = v0 * normcdff(v0); v1 = v1 * normcdff(v1); }
                if (RES)  { v0 += res[(size_t)row * F + col]; v1 += res[(size_t)row * F + col + 1]; }
                if (OUTF16) {
                    *(uint32_t*)(Ch + (size_t)row * F + col) = packh(v0, v1);
                } else {
                    float2 o; o.x = v0; o.y = v1;
                    *(float2*)(C + (size_t)row * F + col) = o;
                }
            }
        }
    }
}

// ---------------- qkv prepass ----------------
__launch_bounds__(256)
__global__ void qkv_prep(const float* __restrict__ qkv,
                         __half* __restrict__ qh, __half* __restrict__ kh,
                         __half* __restrict__ vth) {
    __shared__ float vsm[64][33];
    int nb = blockIdx.x * 64;
    int g = nb >> 10;
    int jb = nb & 1023;
    int tid = threadIdx.x;
    const float scale = 0.17677669529663687f;

#pragma unroll
    for (int it = 0; it < 32; ++it) {
        int flat = tid + it * 256;
        int row = flat >> 7, c4 = flat & 127;
        int node = nb + row;
        float4 v = *(const float4*)&qkv[(size_t)node * QKVD + c4 * 4];
        int c = c4 * 4;
        if (c < 256) {
            *(uint2*)(qh + (size_t)node * HH + c) =
                make_uint2(packh(v.x * scale, v.y * scale), packh(v.z * scale, v.w * scale));
        } else {
            *(uint2*)(kh + (size_t)node * HH + c - 256) =
                make_uint2(packh(v.x, v.y), packh(v.z, v.w));
        }
    }

    for (int h = 0; h < NHEADS; ++h) {
        __syncthreads();
#pragma unroll
        for (int it = 0; it < 2; ++it) {
            int flat = tid + it * 256;
            int row = flat >> 3, c4 = flat & 7;
            float4 v = *(const float4*)&qkv[(size_t)(nb + row) * QKVD + 512 + h * 32 + c4 * 4];
            vsm[row][c4 * 4 + 0] = v.x;
            vsm[row][c4 * 4 + 1] = v.y;
            vsm[row][c4 * 4 + 2] = v.z;
            vsm[row][c4 * 4 + 3] = v.w;
        }
        __syncthreads();
        int d = tid >> 3, j0 = (tid & 7) * 8;
        uint32_t hw[4];
#pragma unroll
        for (int p = 0; p < 4; ++p)
            hw[p] = packh(vsm[j0 + p * 2 + 0][d], vsm[j0 + p * 2 + 1][d]);
        size_t off = ((size_t)(g * NHEADS + h) * HDIM + d) * MM + jb + j0;
        *(uint4*)(vth + off) = make_uint4(hw[0], hw[1], hw[2], hw[3]);
    }
}

// ---------------- flash attention (fp16 single K/V, fp32 accum) ----------------
__launch_bounds__(256)
__global__ void attn_mma(const __half* __restrict__ qh, const __half* __restrict__ kh,
                         const __half* __restrict__ vth,
                         const unsigned char* __restrict__ dist, const float* __restrict__ bias_emb,
                         __half* __restrict__ oh) {
    extern __shared__ unsigned char smp[];
    const int STG = 18944;
    __shared__ float btab[8];
    int gh = blockIdx.x;
    int g = gh >> 3, h = gh & 7;
    int i0 = blockIdx.y * 128;
    int tid = threadIdx.x, lane = tid & 31, warp = tid >> 5;
    int r = lane >> 2, tg = lane & 3;
    if (tid < 7) btab[tid] = bias_emb[tid];
    uint32_t sb = (uint32_t)__cvta_generic_to_shared(smp);
    const float L2E = 1.44269504f;

    int rowA = i0 + warp * 16 + r;
    int rowB = rowA + 8;
    uint32_t qf[2][4];
#pragma unroll
    for (int kc = 0; kc < 2; ++kc) {
        size_t baseA = (size_t)(g * MM + rowA) * HH + h * HDIM + kc * 16 + tg * 2;
        size_t baseB = (size_t)(g * MM + rowB) * HH + h * HDIM + kc * 16 + tg * 2;
        qf[kc][0] = *(const uint32_t*)(qh + baseA);
        qf[kc][1] = *(const uint32_t*)(qh + baseB);
        qf[kc][2] = *(const uint32_t*)(qh + baseA + 8);
        qf[kc][3] = *(const uint32_t*)(qh + baseB + 8);
    }

    float acc_o[4][4];
#pragma unroll
    for (int a = 0; a < 4; ++a)
#pragma unroll
        for (int b = 0; b < 4; ++b) acc_o[a][b] = 0.f;
    float mA = -1e30f, mB = -1e30f, lA = 0.f, lB = 0.f;

    const unsigned char* drowA = dist + ((size_t)(g * MM + rowA)) * MM;
    const unsigned char* drowB = dist + ((size_t)(g * MM + rowB)) * MM;

    auto load_stage = [&](int s, int j0) {
        uint32_t db = sb + s * STG;
#pragma unroll
        for (int c = 0; c < 2; ++c) {
            int t = tid + c * 256;
            int row = t >> 2, ch = t & 3;
            const __half* src = kh + (size_t)(g * MM + j0 + row) * HH + h * HDIM + ch * 8;
            CP16(db + row * 80 + ch * 16, src);
        }
#pragma unroll
        for (int c = 0; c < 2; ++c) {
            int t = tid + c * 256;
            int row = t >> 4, ch = t & 15;
            size_t off = ((size_t)(gh) * HDIM + row) * MM + j0 + ch * 8;
            CP16(db + 10240 + row * 272 + ch * 16, vth + off);
        }
        asm volatile("cp.async.commit_group;\n" ::);
    };

    load_stage(0, 0);
    for (int ch = 0; ch < 8; ++ch) {
        int j0 = ch * 128;
        if (ch < 7) {
            load_stage((ch + 1) & 1, j0 + 128);
            asm volatile("cp.async.wait_group 1;\n" ::);
        } else {
            asm volatile("cp.async.wait_group 0;\n" ::);
        }
        __syncthreads();

        const uint32_t* KH = (const uint32_t*)(smp + (ch & 1) * STG);
        const uint32_t* VH = KH + 2560;

        float acc_s[16][4];
#pragma unroll
        for (int nt = 0; nt < 16; ++nt)
#pragma unroll
            for (int c = 0; c < 4; ++c) acc_s[nt][c] = 0.f;
#pragma unroll
        for (int kc = 0; kc < 2; ++kc) {
#pragma unroll
            for (int nt = 0; nt < 16; ++nt) {
                int idx = (nt * 8 + r) * 20 + kc * 8 + tg;
                MMAH(acc_s[nt], qf[kc][0], qf[kc][1], qf[kc][2], qf[kc][3],
                     KH[idx], KH[idx + 4]);
            }
        }

        float cmA = -1e30f, cmB = -1e30f;
#pragma unroll
        for (int nt = 0; nt < 16; ++nt) {
            uchar2 dA = *(const uchar2*)(drowA + j0 + nt * 8 + tg * 2);
            uchar2 dB = *(const uchar2*)(drowB + j0 + nt * 8 + tg * 2);
            acc_s[nt][0] += btab[dA.x];
            acc_s[nt][1] += btab[dA.y];
            acc_s[nt][2] += btab[dB.x];
            acc_s[nt][3] += btab[dB.y];
            cmA = fmaxf(cmA, fmaxf(acc_s[nt][0], acc_s[nt][1]));
            cmB = fmaxf(cmB, fmaxf(acc_s[nt][2], acc_s[nt][3]));
        }
        cmA = fmaxf(cmA, __shfl_xor_sync(0xFFFFFFFFu, cmA, 1));
        cmA = fmaxf(cmA, __shfl_xor_sync(0xFFFFFFFFu, cmA, 2));
        cmB = fmaxf(cmB, __shfl_xor_sync(0xFFFFFFFFu, cmB, 1));
        cmB = fmaxf(cmB, __shfl_xor_sync(0xFFFFFFFFu, cmB, 2));

        float mAn = fmaxf(mA, cmA), mBn = fmaxf(mB, cmB);
        float corrA = ex2f((mA - mAn) * L2E);
        float corrB = ex2f((mB - mBn) * L2E);
        mA = mAn; mB = mBn;

        uint32_t ph0[16], ph1[16];
        float lsA = 0.f, lsB = 0.f;
#pragma unroll
        for (int nt = 0; nt < 16; ++nt) {
            float p0 = ex2f((acc_s[nt][0] - mA) * L2E);
            float p1 = ex2f((acc_s[nt][1] - mA) * L2E);
            float p2 = ex2f((acc_s[nt][2] - mB) * L2E);
            float p3 = ex2f((acc_s[nt][3] - mB) * L2E);
            lsA += p0 + p1; lsB += p2 + p3;
            ph0[nt] = packh(p0, p1);
            ph1[nt] = packh(p2, p3);
        }
        lsA += __shfl_xor_sync(0xFFFFFFFFu, lsA, 1);
        lsA += __shfl_xor_sync(0xFFFFFFFFu, lsA, 2);
        lsB += __shfl_xor_sync(0xFFFFFFFFu, lsB, 1);
        lsB += __shfl_xor_sync(0xFFFFFFFFu, lsB, 2);
        lA = lA * corrA + lsA;
        lB = lB * corrB + lsB;

#pragma unroll
        for (int nto = 0; nto < 4; ++nto) {
            acc_o[nto][0] *= corrA; acc_o[nto][1] *= corrA;
            acc_o[nto][2] *= corrB; acc_o[nto][3] *= corrB;
        }

#pragma unroll
        for (int kc = 0; kc < 8; ++kc) {
            uint32_t a0 = ph0[2 * kc], a1 = ph1[2 * kc], a2 = ph0[2 * kc + 1], a3 = ph1[2 * kc + 1];
#pragma unroll
            for (int nto = 0; nto < 4; ++nto) {
                int idx = (nto * 8 + r) * 68 + kc * 8 + tg;
                MMAH(acc_o[nto], a0, a1, a2, a3, VH[idx], VH[idx + 4]);
            }
        }
        __syncthreads();
    }

    float invA = 1.f / lA, invB = 1.f / lB;
#pragma unroll
    for (int nto = 0; nto < 4; ++nto) {
        int col = h * HDIM + nto * 8 + tg * 2;
        *(uint32_t*)(oh + (size_t)(g * MM + rowA) * HH + col) =
            packh(acc_o[nto][0] * invA, acc_o[nto][1] * invA);
        *(uint32_t*)(oh + (size_t)(g * MM + rowB) * HH + col) =
            packh(acc_o[nto][2] * invB, acc_o[nto][3] * invB);
    }
}

// ---------------- LayerNorm: warp-per-row, 8 rows per CTA ----------------
__launch_bounds__(256)
__global__ void ln_kernel(const float* __restrict__ a, const float* __restrict__ b,
                          const float* __restrict__ c, const float* __restrict__ gam,
                          const float* __restrict__ bet, float* __restrict__ out,
                          __half* __restrict__ oh) {
    int row = blockIdx.x * 8 + (threadIdx.x >> 5);
    int lane = threadIdx.x & 31;
    size_t idx = (size_t)row * HH + lane * 8;
    float v[8];
    float4 u0 = *(const float4*)&a[idx];
    float4 u1 = *(const float4*)&a[idx + 4];
    v[0] = u0.x; v[1] = u0.y; v[2] = u0.z; v[3] = u0.w;
    v[4] = u1.x; v[5] = u1.y; v[6] = u1.z; v[7] = u1.w;
    if (b) {
        float4 b0 = *(const float4*)&b[idx];
        float4 b1 = *(const float4*)&b[idx + 4];
        v[0] += b0.x; v[1] += b0.y; v[2] += b0.z; v[3] += b0.w;
        v[4] += b1.x; v[5] += b1.y; v[6] += b1.z; v[7] += b1.w;
    }
    if (c) {
        float4 c0 = *(const float4*)&c[idx];
        float4 c1 = *(const float4*)&c[idx + 4];
        v[0] += c0.x; v[1] += c0.y; v[2] += c0.z; v[3] += c0.w;
        v[4] += c1.x; v[5] += c1.y; v[6] += c1.z; v[7] += c1.w;
    }
    float s = 0.f, s2 = 0.f;
#pragma unroll
    for (int j = 0; j < 8; ++j) { s += v[j]; s2 += v[j] * v[j]; }
#pragma unroll
    for (int o = 16; o; o >>= 1) {
        s  += __shfl_xor_sync(0xFFFFFFFFu, s, o);
        s2 += __shfl_xor_sync(0xFFFFFFFFu, s2, o);
    }
    float mean = s * (1.f / HH);
    float var  = s2 * (1.f / HH) - mean * mean;
    float rstd = rsqrtf(var + 1e-5f);
    int gcol = lane * 8;
    float4 g0 = *(const float4*)&gam[gcol];
    float4 g1 = *(const float4*)&gam[gcol + 4];
    float4 e0 = *(const float4*)&bet[gcol];
    float4 e1 = *(const float4*)&bet[gcol + 4];
    float r[8];
    r[0] = (v[0] - mean) * rstd * g0.x + e0.x;
    r[1] = (v[1] - mean) * rstd * g0.y + e0.y;
    r[2] = (v[2] - mean) * rstd * g0.z + e0.z;
    r[3] = (v[3] - mean) * rstd * g0.w + e0.w;
    r[4] = (v[4] - mean) * rstd * g1.x + e1.x;
    r[5] = (v[5] - mean) * rstd * g1.y + e1.y;
    r[6] = (v[6] - mean) * rstd * g1.z + e1.z;
    r[7] = (v[7] - mean) * rstd * g1.w + e1.w;
    float4 o0, o1;
    o0.x = r[0]; o0.y = r[1]; o0.z = r[2]; o0.w = r[3];
    o1.x = r[4]; o1.y = r[5]; o1.z = r[6]; o1.w = r[7];
    *(float4*)&out[idx] = o0;
    *(float4*)&out[idx + 4] = o1;
    if (oh) {
        *(uint4*)(oh + idx) = make_uint4(packh(r[0], r[1]), packh(r[2], r[3]),
                                         packh(r[4], r[5]), packh(r[6], r[7]));
    }
}

// ---------------- fused ln2 + oln1: y = LN(x + xl + LN(tmp)) ----------------
__launch_bounds__(256)
__global__ void ln2_oln1(const float* __restrict__ tmp,
                         const float* __restrict__ l2g, const float* __restrict__ l2b,
                         const float* __restrict__ x, const float* __restrict__ xl,
                         const float* __restrict__ o1g, const float* __restrict__ o1b,
                         float* __restrict__ y, __half* __restrict__ yh) {
    int row = blockIdx.x * 8 + (threadIdx.x >> 5);
    int lane = threadIdx.x & 31;
    size_t idx = (size_t)row * HH + lane * 8;
    int gcol = lane * 8;

    // first LN over tmp
    float v[8];
    float4 u0 = *(const float4*)&tmp[idx];
    float4 u1 = *(const float4*)&tmp[idx + 4];
    v[0]=u0.x; v[1]=u0.y; v[2]=u0.z; v[3]=u0.w;
    v[4]=u1.x; v[5]=u1.y; v[6]=u1.z; v[7]=u1.w;
    float s = 0.f, s2 = 0.f;
#pragma unroll
    for (int j = 0; j < 8; ++j) { s += v[j]; s2 += v[j]*v[j]; }
#pragma unroll
    for (int o = 16; o; o >>= 1) {
        s  += __shfl_xor_sync(0xFFFFFFFFu, s, o);
        s2 += __shfl_xor_sync(0xFFFFFFFFu, s2, o);
    }
    float mean = s * (1.f / HH);
    float rstd = rsqrtf(s2 * (1.f / HH) - mean * mean + 1e-5f);
    float4 g0 = *(const float4*)&l2g[gcol];
    float4 g1 = *(const float4*)&l2g[gcol + 4];
    float4 e0 = *(const float4*)&l2b[gcol];
    float4 e1 = *(const float4*)&l2b[gcol + 4];
    float h2[8];
    h2[0]=(v[0]-mean)*rstd*g0.x+e0.x; h2[1]=(v[1]-mean)*rstd*g0.y+e0.y;
    h2[2]=(v[2]-mean)*rstd*g0.z+e0.z; h2[3]=(v[3]-mean)*rstd*g0.w+e0.w;
    h2[4]=(v[4]-mean)*rstd*g1.x+e1.x; h2[5]=(v[5]-mean)*rstd*g1.y+e1.y;
    h2[6]=(v[6]-mean)*rstd*g1.z+e1.z; h2[7]=(v[7]-mean)*rstd*g1.w+e1.w;

    // second LN over x + xl + h2
    float4 xa0 = *(const float4*)&x[idx];
    float4 xa1 = *(const float4*)&x[idx + 4];
    float4 xb0 = *(const float4*)&xl[idx];
    float4 xb1 = *(const float4*)&xl[idx + 4];
    float u[8];
    u[0]=xa0.x+xb0.x+h2[0]; u[1]=xa0.y+xb0.y+h2[1];
    u[2]=xa0.z+xb0.z+h2[2]; u[3]=xa0.w+xb0.w+h2[3];
    u[4]=xa1.x+xb1.x+h2[4]; u[5]=xa1.y+xb1.y+h2[5];
    u[6]=xa1.z+xb1.z+h2[6]; u[7]=xa1.w+xb1.w+h2[7];
    s = 0.f; s2 = 0.f;
#pragma unroll
    for (int j = 0; j < 8; ++j) { s += u[j]; s2 += u[j]*u[j]; }
#pragma unroll
    for (int o = 16; o; o >>= 1) {
        s  += __shfl_xor_sync(0xFFFFFFFFu, s, o);
        s2 += __shfl_xor_sync(0xFFFFFFFFu, s2, o);
    }
    mean = s * (1.f / HH);
    rstd = rsqrtf(s2 * (1.f / HH) - mean * mean + 1e-5f);
    float4 og0 = *(const float4*)&o1g[gcol];
    float4 og1 = *(const float4*)&o1g[gcol + 4];
    float4 ob0 = *(const float4*)&o1b[gcol];
    float4 ob1 = *(const float4*)&o1b[gcol + 4];
    float r[8];
    r[0]=(u[0]-mean)*rstd*og0.x+ob0.x; r[1]=(u[1]-mean)*rstd*og0.y+ob0.y;
    r[2]=(u[2]-mean)*rstd*og0.z+ob0.z; r[3]=(u[3]-mean)*rstd*og0.w+ob0.w;
    r[4]=(u[4]-mean)*rstd*og1.x+ob1.x; r[5]=(u[5]-mean)*rstd*og1.y+ob1.y;
    r[6]=(u[6]-mean)*rstd*og1.z+ob1.z; r[7]=(u[7]-mean)*rstd*og1.w+ob1.w;
    float4 o0, o1;
    o0.x=r[0]; o0.y=r[1]; o0.z=r[2]; o0.w=r[3];
    o1.x=r[4]; o1.y=r[5]; o1.z=r[6]; o1.w=r[7];
    *(float4*)&y[idx] = o0;
    *(float4*)&y[idx + 4] = o1;
    *(uint4*)(yh + idx) = make_uint4(packh(r[0], r[1]), packh(r[2], r[3]),
                                     packh(r[4], r[5]), packh(r[6], r[7]));
}

// ---------------- host ----------------
static void* sym(const void* s) { void* p = nullptr; cudaGetSymbolAddress(&p, s); return p; }

static cudaStream_t s_s1, s_s2;
static cudaEvent_t  s_evA, s_evXW, s_evSPD, s_evGA;
static struct StreamInit {
    StreamInit() {
        cudaStreamCreateWithFlags(&s_s1, cudaStreamNonBlocking);
        cudaStreamCreateWithFlags(&s_s2, cudaStreamNonBlocking);
        cudaEventCreateWithFlags(&s_evA,   cudaEventDisableTiming);
        cudaEventCreateWithFlags(&s_evXW,  cudaEventDisableTiming);
        cudaEventCreateWithFlags(&s_evSPD, cudaEventDisableTiming);
        cudaEventCreateWithFlags(&s_evGA,  cudaEventDisableTiming);
    }
} s_streamInit;

extern "C" void kernel_launch(void* const* d_in, const int* in_sizes, int n_in,
                              void* d_out, int out_size) {
    const float* x      = (const float*)d_in[0];
    const float* gcn_w  = (const float*)d_in[1];
    const float* gcn_b  = (const float*)d_in[2];
    const float* qkv_w  = (const float*)d_in[3];
    const float* qkv_b  = (const float*)d_in[4];
    const float* proj_w = (const float*)d_in[5];
    const float* proj_b = (const float*)d_in[6];
    const float* ln1_g  = (const float*)d_in[7];
    const float* ln1_b  = (const float*)d_in[8];
    const float* ln2_g  = (const float*)d_in[9];
    const float* ln2_b  = (const float*)d_in[10];
    const float* ffn1_w = (const float*)d_in[11];
    const float* ffn1_b = (const float*)d_in[12];
    const float* ffn2_w = (const float*)d_in[13];
    const float* ffn2_b = (const float*)d_in[14];
    const float* bias_e = (const float*)d_in[15];
    const float* oln1_g = (const float*)d_in[16];
    const float* oln1_b = (const float*)d_in[17];
    const float* oln2_g = (const float*)d_in[18];
    const float* oln2_b = (const float*)d_in[19];
    const float* offn1_w= (const float*)d_in[20];
    const float* offn1_b= (const float*)d_in[21];
    const float* offn2_w= (const float*)d_in[22];
    const float* offn2_b= (const float*)d_in[23];
    const int*   ei     = (const int*)d_in[24];
    int E = in_sizes[24] / 2;

    float*    p_dinv = (float*)sym(g_dinv);
    float*    p_xw   = (float*)sym(g_xw);
    float*    p_xl   = (float*)sym(g_xl);
    uint32_t* p_adj  = (uint32_t*)sym(g_adj);
    uint32_t* p_R2   = (uint32_t*)sym(g_R2);
    uint32_t* p_R3   = (uint32_t*)sym(g_R3);
    uint32_t* p_R4   = (uint32_t*)sym(g_R4);
    uint32_t* p_R5   = (uint32_t*)sym(g_R5);
    unsigned char* p_dist = (unsigned char*)sym(g_dist);
    float*    p_qkv  = (float*)sym(g_qkv);
    float*    p_tmp  = (float*)sym(g_tmp);
    float*    p_h1   = (float*)sym(g_h1);
    float*    p_y    = (float*)sym(g_y);
    int*      p_cnt  = (int*)sym(g_cnt);
    int*      p_base = (int*)sym(g_base);
    int*      p_fill = (int*)sym(g_fillp);
    int*      p_esrc = (int*)sym(g_esrc);
    __half* x_h   = (__half*)sym(g_x_h);
    __half* at_h  = (__half*)sym(g_at_h);
    __half* h1_h  = (__half*)sym(g_h1_h);
    __half* y_h   = (__half*)sym(g_y_h);
    __half* mid_h = (__half*)sym(g_mid_h);
    __half* q_h   = (__half*)sym(g_q_h);
    __half* k_h   = (__half*)sym(g_k_h);
    __half* vt_h  = (__half*)sym(g_vt_h);
    __half* whi   = (__half*)sym(g_whi);
    float* out = (float*)d_out;

    const int SMEM  = 40960;
    const int ASMEM = 37888;
    cudaFuncSetAttribute(gemm_f16<0,0,0>, cudaFuncAttributeMaxDynamicSharedMemorySize, SMEM);
    cudaFuncSetAttribute(gemm_f16<0,1,0>, cudaFuncAttributeMaxDynamicSharedMemorySize, SMEM);
    cudaFuncSetAttribute(gemm_f16<1,0,1>, cudaFuncAttributeMaxDynamicSharedMemorySize, SMEM);
    cudaFuncSetAttribute(attn_mma, cudaFuncAttributeMaxDynamicSharedMemorySize, ASMEM);

    // --- default stream: counts + adjacency, then fork ---
    zero_prep<<<(GG * MM * 32 + 255) / 256, 256>>>(p_cnt, p_adj);
    edge_prep<<<(E + 255) / 256, 256>>>(ei, E, p_cnt, p_adj);
    cudaEventRecord(s_evA, 0);

    // --- s1: SPD chain ---
    cudaStreamWaitEvent(s_s1, s_evA, 0);
    spd_round<<<NN * 32 / 256, 256, 0, s_s1>>>(p_adj, p_adj, p_R2);
    spd_round<<<NN * 32 / 256, 256, 0, s_s1>>>(p_adj, p_R2, p_R3);
    spd_round<<<NN * 32 / 256, 256, 0, s_s1>>>(p_adj, p_R3, p_R4);
    spd_round<<<NN * 32 / 256, 256, 0, s_s1>>>(p_adj, p_R4, p_R5);
    spd_final<<<NN * 32 / 256, 256, 0, s_s1>>>(p_adj, p_R2, p_R3, p_R4, p_R5, p_dist);
    cudaEventRecord(s_evSPD, s_s1);

    // --- s2: edge CSR + GCN gather ---
    cudaStreamWaitEvent(s_s2, s_evA, 0);
    scan_kernel<<<1, 1024, 0, s_s2>>>(p_cnt, p_base, p_fill, p_dinv);
    fill_edges<<<(E + 255) / 256, 256, 0, s_s2>>>(ei, E, p_fill, p_esrc);

    // --- default stream: splits + GEMM chain ---
    splitw<<<(344064 + 255) / 256, 256>>>((const float4*)gcn_w, (const float4*)qkv_w,
        (const float4*)proj_w, (const float4*)ffn1_w, (const float4*)ffn2_w,
        (const float4*)offn1_w, (const float4*)offn2_w, whi);
    splitx<<<(NN * HH / 4 + 255) / 256, 256>>>((const float4*)x, x_h, NN * HH / 4);
    gemm_f16<0,0,0><<<dim3(NN/128, HH/128), 256, SMEM>>>(x_h, whi + OFF_GCN,
        nullptr, nullptr, p_xw, nullptr, HH, HH);
    cudaEventRecord(s_evXW, 0);
    cudaStreamWaitEvent(s_s2, s_evXW, 0);
    gcn_gather<<<NN / 4, 256, 0, s_s2>>>(p_xw, p_dinv, p_base, p_cnt, p_esrc, gcn_b, p_xl);
    cudaEventRecord(s_evGA, s_s2);

    gemm_f16<0,0,0><<<dim3(NN/128, QKVD/128), 256, SMEM>>>(x_h, whi + OFF_QKV,
        qkv_b, nullptr, p_qkv, nullptr, HH, QKVD);
    qkv_prep<<<NN / 64, 256>>>(p_qkv, q_h, k_h, vt_h);

    cudaStreamWaitEvent(0, s_evSPD, 0);
    attn_mma<<<dim3(GG * NHEADS, MM / 128), 256, ASMEM>>>(q_h, k_h, vt_h, p_dist, bias_e, at_h);
    gemm_f16<0,1,0><<<dim3(NN/128, HH/128), 256, SMEM>>>(at_h, whi + OFF_PROJ,
        proj_b, x, p_tmp, nullptr, HH, HH);
    ln_kernel<<<NN / 8, 256>>>(p_tmp, nullptr, nullptr, ln1_g, ln1_b, p_h1, h1_h);
    gemm_f16<1,0,1><<<dim3(NN/128, FFND/128), 256, SMEM>>>(h1_h, whi + OFF_FFN1,
        ffn1_b, nullptr, nullptr, mid_h, HH, FFND);
    gemm_f16<0,1,0><<<dim3(NN/128, HH/128), 256, SMEM>>>(mid_h, whi + OFF_FFN2,
        ffn2_b, p_h1, p_tmp, nullptr, FFND, HH);

    // --- fused ln2 + GPS-combine oln1 (needs xl from s2) ---
    cudaStreamWaitEvent(0, s_evGA, 0);
    ln2_oln1<<<NN / 8, 256>>>(p_tmp, ln2_g, ln2_b, x, p_xl, oln1_g, oln1_b, p_y, y_h);
    gemm_f16<1,0,1><<<dim3(NN/128, FFND/128), 256, SMEM>>>(y_h, whi + OFF_OFFN1,
        offn1_b, nullptr, nullptr, mid_h, HH, FFND);
    gemm_f16<0,1,0><<<dim3(NN/128, HH/128), 256, SMEM>>>(mid_h, whi + OFF_OFFN2,
        offn2_b, p_y, p_tmp, nullptr, FFND, HH);
    ln_kernel<<<NN / 8, 256>>>(p_tmp, nullptr, nullptr, oln2_g, oln2_b, out, nullptr);
}

// round 16
// speedup vs baseline: 1.0817x; 1.0152x over previous
#include <cuda_runtime.h>
#include <cuda_fp16.h>
#include <cstdint>
#include <math.h>

#define GG 8
#define MM 1024
#define NN 8192
#define HH 256
#define NHEADS 8
#define HDIM 32
#define FFND 1024
#define QKVD 768

// ---------------- scratch ----------------
__device__ float    g_dinv[NN];
__device__ float    g_xw  [NN * HH];
__device__ float    g_xl  [NN * HH];
__device__ uint32_t g_adj [GG * MM * 32];
__device__ uint32_t g_R2  [GG * MM * 32];
__device__ uint32_t g_R3  [GG * MM * 32];
__device__ uint32_t g_R4  [GG * MM * 32];
__device__ uint32_t g_R5  [GG * MM * 32];
__device__ unsigned char g_dist[(size_t)GG * MM * MM];
__device__ float    g_qkv [(size_t)NN * QKVD];
__device__ float    g_tmp [NN * HH];
__device__ float    g_h1  [NN * HH];
__device__ float    g_y   [NN * HH];
__device__ int      g_cnt [NN];
__device__ int      g_base[NN];
__device__ int      g_fillp[NN];
__device__ int      g_esrc[262144];

#define AL16 __align__(16)
__device__ AL16 __half g_x_h [NN * HH];
__device__ AL16 __half g_at_h[NN * HH];
__device__ AL16 __half g_h1_h[NN * HH];
__device__ AL16 __half g_y_h [NN * HH];
__device__ AL16 __half g_mid_h[(size_t)NN * FFND];
__device__ AL16 __half g_q_h [NN * HH];
__device__ AL16 __half g_k_h [NN * HH];
__device__ AL16 __half g_vt_h[GG * NHEADS * HDIM * MM];
__device__ AL16 __half g_whi[1376256];
#define OFF_GCN   0
#define OFF_QKV   65536
#define OFF_PROJ  262144
#define OFF_FFN1  327680
#define OFF_FFN2  589824
#define OFF_OFFN1 851968
#define OFF_OFFN2 1114112

// ---------------- helpers ----------------
__device__ __forceinline__ uint32_t packh(float a, float b) {
    uint32_t r;
    asm("cvt.rn.f16x2.f32 %0, %1, %2;" : "=r"(r) : "f"(b), "f"(a));
    return r;
}
__device__ __forceinline__ float ex2f(float x) {
    float y; asm("ex2.approx.f32 %0, %1;" : "=f"(y) : "f"(x)); return y;
}
#define CP16(dst, src) asm volatile("cp.async.cg.shared.global [%0], [%1], 16;\n" :: "r"(dst), "l"(src))
#define MMAH(d, a0, a1, a2, a3, b0, b1) \
    asm volatile("mma.sync.aligned.m16n8k16.row.col.f32.f16.f16.f32 " \
                 "{%0,%1,%2,%3}, {%4,%5,%6,%7}, {%8,%9}, {%0,%1,%2,%3};" \
                 : "+f"(d[0]), "+f"(d[1]), "+f"(d[2]), "+f"(d[3]) \
                 : "r"(a0), "r"(a1), "r"(a2), "r"(a3), "r"(b0), "r"(b1))
#define LDSM4(r0, r1, r2, r3, addr) \
    asm volatile("ldmatrix.sync.aligned.m8n8.x4.shared.b16 {%0,%1,%2,%3}, [%4];" \
                 : "=r"(r0), "=r"(r1), "=r"(r2), "=r"(r3) : "r"(addr))

// ---------------- splits (plain fp16 cast) ----------------
__global__ void splitx(const float4* __restrict__ in, __half* __restrict__ hi, int n4) {
    int i = blockIdx.x * blockDim.x + threadIdx.x;
    if (i >= n4) return;
    float4 v = in[i];
    *(uint2*)(hi + i * 4) = make_uint2(packh(v.x, v.y), packh(v.z, v.w));
}
__global__ void splitw(const float4* w0, const float4* w1, const float4* w2, const float4* w3,
                       const float4* w4, const float4* w5, const float4* w6,
                       __half* __restrict__ hi) {
    int i = blockIdx.x * blockDim.x + threadIdx.x;
    if (i >= 344064) return;
    const float4* src; int base;
    if      (i < 16384)  { src = w0; base = 0; }
    else if (i < 65536)  { src = w1; base = 16384; }
    else if (i < 81920)  { src = w2; base = 65536; }
    else if (i < 147456) { src = w3; base = 81920; }
    else if (i < 212992) { src = w4; base = 147456; }
    else if (i < 278528) { src = w5; base = 212992; }
    else                 { src = w6; base = 278528; }
    float4 v = src[i - base];
    *(uint2*)(hi + (size_t)i * 4) = make_uint2(packh(v.x, v.y), packh(v.z, v.w));
}

// ---------------- graph prep ----------------
__global__ void zero_prep(int* __restrict__ cnt, uint32_t* __restrict__ adj) {
    int i = blockIdx.x * blockDim.x + threadIdx.x;
    if (i < GG * MM * 32) adj[i] = 0u;
    if (i < NN) cnt[i] = 0;
}
__global__ void edge_prep(const int* __restrict__ ei, int E, int* __restrict__ cnt,
                          uint32_t* __restrict__ adj) {
    int e = blockIdx.x * blockDim.x + threadIdx.x;
    if (e >= E) return;
    int s = ei[e], d = ei[E + e];
    atomicAdd(&cnt[d], 1);
    if (s == d || (s >> 10) != (d >> 10)) return;
    int g = s >> 10, ls = s & 1023, ld = d & 1023;
    atomicOr(&adj[((size_t)g * MM + ls) * 32 + (ld >> 5)], 1u << (ld & 31));
    atomicOr(&adj[((size_t)g * MM + ld) * 32 + (ls >> 5)], 1u << (ls & 31));
}
__global__ void scan_kernel(const int* __restrict__ cnt, int* __restrict__ base,
                            int* __restrict__ fillp, float* __restrict__ dinv) {
    __shared__ int wsum[32];
    int t = threadIdx.x;
    int v[8]; int s = 0;
#pragma unroll
    for (int k = 0; k < 8; ++k) { v[k] = s; s += cnt[t * 8 + k]; }
    int lane = t & 31, w = t >> 5;
    int tot = s, sc = s;
#pragma unroll
    for (int o = 1; o < 32; o <<= 1) {
        int n = __shfl_up_sync(0xFFFFFFFFu, sc, o);
        if (lane >= o) sc += n;
    }
    if (lane == 31) wsum[w] = sc;
    __syncthreads();
    if (w == 0) {
        int x = wsum[lane];
#pragma unroll
        for (int o = 1; o < 32; o <<= 1) {
            int n = __shfl_up_sync(0xFFFFFFFFu, x, o);
            if (lane >= o) x += n;
        }
        wsum[lane] = x;
    }
    __syncthreads();
    int excl = sc - tot + (w > 0 ? wsum[w - 1] : 0);
#pragma unroll
    for (int k = 0; k < 8; ++k) {
        int idx = t * 8 + k;
        int b = excl + v[k];
        base[idx] = b;
        fillp[idx] = b;
        dinv[idx] = rsqrtf((float)cnt[idx] + 1.0f);
    }
}
__global__ void fill_edges(const int* __restrict__ ei, int E, int* __restrict__ fillp,
                           int* __restrict__ esrc) {
    int e = blockIdx.x * blockDim.x + threadIdx.x;
    if (e >= E) return;
    int s = ei[e], d = ei[E + e];
    int pos = atomicAdd(&fillp[d], 1);
    esrc[pos] = s;
}
__launch_bounds__(256)
__global__ void gcn_gather(const float* __restrict__ xw, const float* __restrict__ dinv,
                           const int* __restrict__ base, const int* __restrict__ cnt,
                           const int* __restrict__ esrc, const float* __restrict__ gcn_b,
                           float* __restrict__ xl) {
    int node = blockIdx.x * 4 + (threadIdx.x >> 6);
    int c4 = (threadIdx.x & 63) * 4;
    float dd = dinv[node];
    float4 v0 = *(const float4*)&xw[(size_t)node * HH + c4];
    float ax = dd * v0.x, ay = dd * v0.y, az = dd * v0.z, aw = dd * v0.w;
    int b0 = __ldg(&base[node]);
    int n  = __ldg(&cnt[node]);
    int k = 0;
    for (; k + 4 <= n; k += 4) {
        int s0 = __ldg(&esrc[b0 + k]);
        int s1 = __ldg(&esrc[b0 + k + 1]);
        int s2 = __ldg(&esrc[b0 + k + 2]);
        int s3 = __ldg(&esrc[b0 + k + 3]);
        float w0 = __ldg(&dinv[s0]), w1 = __ldg(&dinv[s1]);
        float w2 = __ldg(&dinv[s2]), w3 = __ldg(&dinv[s3]);
        float4 a = *(const float4*)&xw[(size_t)s0 * HH + c4];
        float4 b = *(const float4*)&xw[(size_t)s1 * HH + c4];
        float4 c = *(const float4*)&xw[(size_t)s2 * HH + c4];
        float4 d = *(const float4*)&xw[(size_t)s3 * HH + c4];
        ax += w0 * a.x + w1 * b.x + w2 * c.x + w3 * d.x;
        ay += w0 * a.y + w1 * b.y + w2 * c.y + w3 * d.y;
        az += w0 * a.z + w1 * b.z + w2 * c.z + w3 * d.z;
        aw += w0 * a.w + w1 * b.w + w2 * c.w + w3 * d.w;
    }
    for (; k < n; ++k) {
        int s = __ldg(&esrc[b0 + k]);
        float ws = __ldg(&dinv[s]);
        float4 v = *(const float4*)&xw[(size_t)s * HH + c4];
        ax += ws * v.x; ay += ws * v.y; az += ws * v.z; aw += ws * v.w;
    }
    float4 bia = *(const float4*)&gcn_b[c4];
    float4 o;
    o.x = dd * ax + bia.x; o.y = dd * ay + bia.y;
    o.z = dd * az + bia.z; o.w = dd * aw + bia.w;
    *(float4*)&xl[(size_t)node * HH + c4] = o;
}

// ---------------- SPD: boolean matrix powers, warp-per-row ----------------
__launch_bounds__(256)
__global__ void spd_round(const uint32_t* __restrict__ adj, const uint32_t* __restrict__ Rp,
                          uint32_t* __restrict__ Rn) {
    int gw = (blockIdx.x * 256 + threadIdx.x) >> 5;
    int lane = threadIdx.x & 31;
    int g = gw >> 10, i = gw & 1023;
    const uint32_t* Rg = Rp + (size_t)g * MM * 32;
    uint32_t a = adj[((size_t)g * MM + i) * 32 + lane];
    uint32_t nw = Rg[i * 32 + lane];
    for (int w = 0; w < 32; ++w) {
        uint32_t f = __shfl_sync(0xFFFFFFFFu, a, w);
        while (f) {
            int b = __ffs((int)f) - 1;
            f &= f - 1;
            nw |= Rg[(w * 32 + b) * 32 + lane];
        }
    }
    Rn[((size_t)g * MM + i) * 32 + lane] = nw;
}
__device__ __forceinline__ uint32_t nibspread(uint32_t r, int q) {
    return (((r >> (q * 4)) & 0xFu) * 0x00204081u) & 0x01010101u;
}
__launch_bounds__(256)
__global__ void spd_final(const uint32_t* __restrict__ R1, const uint32_t* __restrict__ R2,
                          const uint32_t* __restrict__ R3, const uint32_t* __restrict__ R4,
                          const uint32_t* __restrict__ R5, unsigned char* __restrict__ dist) {
    int idx = blockIdx.x * 256 + threadIdx.x;
    int row = idx >> 5, w = idx & 31;
    uint32_t r1 = R1[idx], r2 = R2[idx], r3 = R3[idx], r4 = R4[idx], r5 = R5[idx];
    unsigned char* drow = dist + (size_t)row * MM;
    uint4* dp = (uint4*)(drow + w * 32);
    uint32_t o[8];
#pragma unroll
    for (int q = 0; q < 8; ++q) {
        uint32_t s = nibspread(r1, q) + nibspread(r2, q) + nibspread(r3, q)
                   + nibspread(r4, q) + nibspread(r5, q);
        o[q] = 0x06060606u - s;
    }
    dp[0] = make_uint4(o[0], o[1], o[2], o[3]);
    dp[1] = make_uint4(o[4], o[5], o[6], o[7]);
    int i = row & 1023;
    if ((i >> 5) == w) drow[i] = 0;
}

// ---------------- fp16 GEMM 128x128 (ldmatrix, fp32 accum) ----------------
template <int GELU, int RES, int OUTF16>
__launch_bounds__(256, 2)
__global__ void gemm_f16(const __half* __restrict__ Ag, const __half* __restrict__ Whg,
                         const float* __restrict__ bias, const float* __restrict__ res,
                         float* __restrict__ C, __half* __restrict__ Ch, int K, int F) {
    extern __shared__ unsigned char smp[];
    const int STG = 20480;
    int m0 = blockIdx.x * 128, f0 = blockIdx.y * 128;
    int tid = threadIdx.x, lane = tid & 31, warp = tid >> 5;
    int g = lane >> 2, tg = lane & 3;
    int wm = (warp >> 2) * 64, wn = (warp & 3) * 32;
    uint32_t smem_base = (uint32_t)__cvta_generic_to_shared(smp);

    uint32_t aOff = (uint32_t)(wm + (lane & 15)) * 80 + (uint32_t)(lane >> 4) * 16;
    uint32_t bOff = (uint32_t)(wn + ((lane >> 4) << 3) + (lane & 7)) * 80
                  + (uint32_t)((lane >> 3) & 1) * 16;

    float acc[4][4][4];
#pragma unroll
    for (int a = 0; a < 4; ++a)
#pragma unroll
        for (int b = 0; b < 4; ++b)
#pragma unroll
            for (int c = 0; c < 4; ++c) acc[a][b][c] = 0.f;

    auto load_stage = [&](int s, int k0) {
        uint32_t db = smem_base + s * STG;
        const __half* srcs[2] = { Ag + (size_t)m0 * K + k0, Whg + (size_t)f0 * K + k0 };
#pragma unroll
        for (int arr = 0; arr < 2; ++arr) {
            const __half* bp = srcs[arr];
            uint32_t ab = db + arr * 10240;
#pragma unroll
            for (int c = 0; c < 2; ++c) {
                int t = tid + c * 256;
                int row = t >> 2, ch = t & 3;
                CP16(ab + row * 80 + ch * 16, bp + (size_t)row * K + ch * 8);
            }
        }
        asm volatile("cp.async.commit_group;\n" ::);
    };

    int nk = K >> 5;
    load_stage(0, 0);
    for (int kc = 0; kc < nk; ++kc) {
        if (kc + 1 < nk) {
            load_stage((kc + 1) & 1, (kc + 1) << 5);
            asm volatile("cp.async.wait_group 1;\n" ::);
        } else {
            asm volatile("cp.async.wait_group 0;\n" ::);
        }
        __syncthreads();

        uint32_t stg = smem_base + (kc & 1) * STG;
        uint32_t aB  = stg + aOff;
        uint32_t whB = stg + 10240 + bOff;
#pragma unroll
        for (int ks = 0; ks < 2; ++ks) {
            uint32_t bh[4][2];
            LDSM4(bh[0][0], bh[0][1], bh[1][0], bh[1][1], whB + ks * 32);
            LDSM4(bh[2][0], bh[2][1], bh[3][0], bh[3][1], whB + 1280 + ks * 32);
#pragma unroll
            for (int mt = 0; mt < 4; ++mt) {
                uint32_t a0, a1, a2, a3;
                LDSM4(a0, a1, a2, a3, aB + mt * 1280 + ks * 32);
#pragma unroll
                for (int nt = 0; nt < 4; ++nt)
                    MMAH(acc[mt][nt], a0, a1, a2, a3, bh[nt][0], bh[nt][1]);
            }
        }
        __syncthreads();
    }

#pragma unroll
    for (int mt = 0; mt < 4; ++mt) {
#pragma unroll
        for (int half = 0; half < 2; ++half) {
            int row = m0 + wm + mt * 16 + g + half * 8;
#pragma unroll
            for (int nt = 0; nt < 4; ++nt) {
                int col = f0 + wn + nt * 8 + tg * 2;
                float v0 = acc[mt][nt][half * 2 + 0];
                float v1 = acc[mt][nt][half * 2 + 1];
                if (bias) { v0 += bias[col]; v1 += bias[col + 1]; }
                if (GELU) { v0 = v0 * normcdff(v0); v1 = v1 * normcdff(v1); }
                if (RES)  { v0 += res[(size_t)row * F + col]; v1 += res[(size_t)row * F + col + 1]; }
                if (OUTF16) {
                    *(uint32_t*)(Ch + (size_t)row * F + col) = packh(v0, v1);
                } else {
                    float2 o; o.x = v0; o.y = v1;
                    *(float2*)(C + (size_t)row * F + col) = o;
                }
            }
        }
    }
}

// ---------------- qkv prepass ----------------
__launch_bounds__(256)
__global__ void qkv_prep(const float* __restrict__ qkv,
                         __half* __restrict__ qh, __half* __restrict__ kh,
                         __half* __restrict__ vth) {
    __shared__ float vsm[64][33];
    int nb = blockIdx.x * 64;
    int g = nb >> 10;
    int jb = nb & 1023;
    int tid = threadIdx.x;
    const float scale = 0.17677669529663687f;

#pragma unroll
    for (int it = 0; it < 32; ++it) {
        int flat = tid + it * 256;
        int row = flat >> 7, c4 = flat & 127;
        int node = nb + row;
        float4 v = *(const float4*)&qkv[(size_t)node * QKVD + c4 * 4];
        int c = c4 * 4;
        if (c < 256) {
            *(uint2*)(qh + (size_t)node * HH + c) =
                make_uint2(packh(v.x * scale, v.y * scale), packh(v.z * scale, v.w * scale));
        } else {
            *(uint2*)(kh + (size_t)node * HH + c - 256) =
                make_uint2(packh(v.x, v.y), packh(v.z, v.w));
        }
    }

    for (int h = 0; h < NHEADS; ++h) {
        __syncthreads();
#pragma unroll
        for (int it = 0; it < 2; ++it) {
            int flat = tid + it * 256;
            int row = flat >> 3, c4 = flat & 7;
            float4 v = *(const float4*)&qkv[(size_t)(nb + row) * QKVD + 512 + h * 32 + c4 * 4];
            vsm[row][c4 * 4 + 0] = v.x;
            vsm[row][c4 * 4 + 1] = v.y;
            vsm[row][c4 * 4 + 2] = v.z;
            vsm[row][c4 * 4 + 3] = v.w;
        }
        __syncthreads();
        int d = tid >> 3, j0 = (tid & 7) * 8;
        uint32_t hw[4];
#pragma unroll
        for (int p = 0; p < 4; ++p)
            hw[p] = packh(vsm[j0 + p * 2 + 0][d], vsm[j0 + p * 2 + 1][d]);
        size_t off = ((size_t)(g * NHEADS + h) * HDIM + d) * MM + jb + j0;
        *(uint4*)(vth + off) = make_uint4(hw[0], hw[1], hw[2], hw[3]);
    }
}

// ---------------- flash attention (fp16 single K/V, fp32 accum) ----------------
__launch_bounds__(256)
__global__ void attn_mma(const __half* __restrict__ qh, const __half* __restrict__ kh,
                         const __half* __restrict__ vth,
                         const unsigned char* __restrict__ dist, const float* __restrict__ bias_emb,
                         __half* __restrict__ oh) {
    extern __shared__ unsigned char smp[];
    const int STG = 18944;
    __shared__ float btab[8];
    int gh = blockIdx.x;
    int g = gh >> 3, h = gh & 7;
    int i0 = blockIdx.y * 128;
    int tid = threadIdx.x, lane = tid & 31, warp = tid >> 5;
    int r = lane >> 2, tg = lane & 3;
    if (tid < 7) btab[tid] = bias_emb[tid];
    uint32_t sb = (uint32_t)__cvta_generic_to_shared(smp);
    const float L2E = 1.44269504f;

    int rowA = i0 + warp * 16 + r;
    int rowB = rowA + 8;
    uint32_t qf[2][4];
#pragma unroll
    for (int kc = 0; kc < 2; ++kc) {
        size_t baseA = (size_t)(g * MM + rowA) * HH + h * HDIM + kc * 16 + tg * 2;
        size_t baseB = (size_t)(g * MM + rowB) * HH + h * HDIM + kc * 16 + tg * 2;
        qf[kc][0] = *(const uint32_t*)(qh + baseA);
        qf[kc][1] = *(const uint32_t*)(qh + baseB);
        qf[kc][2] = *(const uint32_t*)(qh + baseA + 8);
        qf[kc][3] = *(const uint32_t*)(qh + baseB + 8);
    }

    float acc_o[4][4];
#pragma unroll
    for (int a = 0; a < 4; ++a)
#pragma unroll
        for (int b = 0; b < 4; ++b) acc_o[a][b] = 0.f;
    float mA = -1e30f, mB = -1e30f, lA = 0.f, lB = 0.f;

    const unsigned char* drowA = dist + ((size_t)(g * MM + rowA)) * MM;
    const unsigned char* drowB = dist + ((size_t)(g * MM + rowB)) * MM;

    auto load_stage = [&](int s, int j0) {
        uint32_t db = sb + s * STG;
#pragma unroll
        for (int c = 0; c < 2; ++c) {
            int t = tid + c * 256;
            int row = t >> 2, ch = t & 3;
            const __half* src = kh + (size_t)(g * MM + j0 + row) * HH + h * HDIM + ch * 8;
            CP16(db + row * 80 + ch * 16, src);
        }
#pragma unroll
        for (int c = 0; c < 2; ++c) {
            int t = tid + c * 256;
            int row = t >> 4, ch = t & 15;
            size_t off = ((size_t)(gh) * HDIM + row) * MM + j0 + ch * 8;
            CP16(db + 10240 + row * 272 + ch * 16, vth + off);
        }
        asm volatile("cp.async.commit_group;\n" ::);
    };

    load_stage(0, 0);
    for (int ch = 0; ch < 8; ++ch) {
        int j0 = ch * 128;
        if (ch < 7) {
            load_stage((ch + 1) & 1, j0 + 128);
            asm volatile("cp.async.wait_group 1;\n" ::);
        } else {
            asm volatile("cp.async.wait_group 0;\n" ::);
        }
        __syncthreads();

        const uint32_t* KH = (const uint32_t*)(smp + (ch & 1) * STG);
        const uint32_t* VH = KH + 2560;

        float acc_s[16][4];
#pragma unroll
        for (int nt = 0; nt < 16; ++nt)
#pragma unroll
            for (int c = 0; c < 4; ++c) acc_s[nt][c] = 0.f;
#pragma unroll
        for (int kc = 0; kc < 2; ++kc) {
#pragma unroll
            for (int nt = 0; nt < 16; ++nt) {
                int idx = (nt * 8 + r) * 20 + kc * 8 + tg;
                MMAH(acc_s[nt], qf[kc][0], qf[kc][1], qf[kc][2], qf[kc][3],
                     KH[idx], KH[idx + 4]);
            }
        }

        float cmA = -1e30f, cmB = -1e30f;
#pragma unroll
        for (int nt = 0; nt < 16; ++nt) {
            uchar2 dA = *(const uchar2*)(drowA + j0 + nt * 8 + tg * 2);
            uchar2 dB = *(const uchar2*)(drowB + j0 + nt * 8 + tg * 2);
            acc_s[nt][0] += btab[dA.x];
            acc_s[nt][1] += btab[dA.y];
            acc_s[nt][2] += btab[dB.x];
            acc_s[nt][3] += btab[dB.y];
            cmA = fmaxf(cmA, fmaxf(acc_s[nt][0], acc_s[nt][1]));
            cmB = fmaxf(cmB, fmaxf(acc_s[nt][2], acc_s[nt][3]));
        }
        cmA = fmaxf(cmA, __shfl_xor_sync(0xFFFFFFFFu, cmA, 1));
        cmA = fmaxf(cmA, __shfl_xor_sync(0xFFFFFFFFu, cmA, 2));
        cmB = fmaxf(cmB, __shfl_xor_sync(0xFFFFFFFFu, cmB, 1));
        cmB = fmaxf(cmB, __shfl_xor_sync(0xFFFFFFFFu, cmB, 2));

        float mAn = fmaxf(mA, cmA), mBn = fmaxf(mB, cmB);
        float corrA = ex2f((mA - mAn) * L2E);
        float corrB = ex2f((mB - mBn) * L2E);
        mA = mAn; mB = mBn;

        uint32_t ph0[16], ph1[16];
        float lsA = 0.f, lsB = 0.f;
#pragma unroll
        for (int nt = 0; nt < 16; ++nt) {
            float p0 = ex2f((acc_s[nt][0] - mA) * L2E);
            float p1 = ex2f((acc_s[nt][1] - mA) * L2E);
            float p2 = ex2f((acc_s[nt][2] - mB) * L2E);
            float p3 = ex2f((acc_s[nt][3] - mB) * L2E);
            lsA += p0 + p1; lsB += p2 + p3;
            ph0[nt] = packh(p0, p1);
            ph1[nt] = packh(p2, p3);
        }
        lsA += __shfl_xor_sync(0xFFFFFFFFu, lsA, 1);
        lsA += __shfl_xor_sync(0xFFFFFFFFu, lsA, 2);
        lsB += __shfl_xor_sync(0xFFFFFFFFu, lsB, 1);
        lsB += __shfl_xor_sync(0xFFFFFFFFu, lsB, 2);
        lA = lA * corrA + lsA;
        lB = lB * corrB + lsB;

#pragma unroll
        for (int nto = 0; nto < 4; ++nto) {
            acc_o[nto][0] *= corrA; acc_o[nto][1] *= corrA;
            acc_o[nto][2] *= corrB; acc_o[nto][3] *= corrB;
        }

#pragma unroll
        for (int kc = 0; kc < 8; ++kc) {
            uint32_t a0 = ph0[2 * kc], a1 = ph1[2 * kc], a2 = ph0[2 * kc + 1], a3 = ph1[2 * kc + 1];
#pragma unroll
            for (int nto = 0; nto < 4; ++nto) {
                int idx = (nto * 8 + r) * 68 + kc * 8 + tg;
                MMAH(acc_o[nto], a0, a1, a2, a3, VH[idx], VH[idx + 4]);
            }
        }
        __syncthreads();
    }

    float invA = 1.f / lA, invB = 1.f / lB;
#pragma unroll
    for (int nto = 0; nto < 4; ++nto) {
        int col = h * HDIM + nto * 8 + tg * 2;
        *(uint32_t*)(oh + (size_t)(g * MM + rowA) * HH + col) =
            packh(acc_o[nto][0] * invA, acc_o[nto][1] * invA);
        *(uint32_t*)(oh + (size_t)(g * MM + rowB) * HH + col) =
            packh(acc_o[nto][2] * invB, acc_o[nto][3] * invB);
    }
}

// ---------------- LayerNorm: warp-per-row, 8 rows per CTA ----------------
__launch_bounds__(256)
__global__ void ln_kernel(const float* __restrict__ a, const float* __restrict__ b,
                          const float* __restrict__ c, const float* __restrict__ gam,
                          const float* __restrict__ bet, float* __restrict__ out,
                          __half* __restrict__ oh) {
    int row = blockIdx.x * 8 + (threadIdx.x >> 5);
    int lane = threadIdx.x & 31;
    size_t idx = (size_t)row * HH + lane * 8;
    float v[8];
    float4 u0 = *(const float4*)&a[idx];
    float4 u1 = *(const float4*)&a[idx + 4];
    v[0] = u0.x; v[1] = u0.y; v[2] = u0.z; v[3] = u0.w;
    v[4] = u1.x; v[5] = u1.y; v[6] = u1.z; v[7] = u1.w;
    if (b) {
        float4 b0 = *(const float4*)&b[idx];
        float4 b1 = *(const float4*)&b[idx + 4];
        v[0] += b0.x; v[1] += b0.y; v[2] += b0.z; v[3] += b0.w;
        v[4] += b1.x; v[5] += b1.y; v[6] += b1.z; v[7] += b1.w;
    }
    if (c) {
        float4 c0 = *(const float4*)&c[idx];
        float4 c1 = *(const float4*)&c[idx + 4];
        v[0] += c0.x; v[1] += c0.y; v[2] += c0.z; v[3] += c0.w;
        v[4] += c1.x; v[5] += c1.y; v[6] += c1.z; v[7] += c1.w;
    }
    float s = 0.f, s2 = 0.f;
#pragma unroll
    for (int j = 0; j < 8; ++j) { s += v[j]; s2 += v[j] * v[j]; }
#pragma unroll
    for (int o = 16; o; o >>= 1) {
        s  += __shfl_xor_sync(0xFFFFFFFFu, s, o);
        s2 += __shfl_xor_sync(0xFFFFFFFFu, s2, o);
    }
    float mean = s * (1.f / HH);
    float var  = s2 * (1.f / HH) - mean * mean;
    float rstd = rsqrtf(var + 1e-5f);
    int gcol = lane * 8;
    float4 g0 = *(const float4*)&gam[gcol];
    float4 g1 = *(const float4*)&gam[gcol + 4];
    float4 e0 = *(const float4*)&bet[gcol];
    float4 e1 = *(const float4*)&bet[gcol + 4];
    float r[8];
    r[0] = (v[0] - mean) * rstd * g0.x + e0.x;
    r[1] = (v[1] - mean) * rstd * g0.y + e0.y;
    r[2] = (v[2] - mean) * rstd * g0.z + e0.z;
    r[3] = (v[3] - mean) * rstd * g0.w + e0.w;
    r[4] = (v[4] - mean) * rstd * g1.x + e1.x;
    r[5] = (v[5] - mean) * rstd * g1.y + e1.y;
    r[6] = (v[6] - mean) * rstd * g1.z + e1.z;
    r[7] = (v[7] - mean) * rstd * g1.w + e1.w;
    float4 o0, o1;
    o0.x = r[0]; o0.y = r[1]; o0.z = r[2]; o0.w = r[3];
    o1.x = r[4]; o1.y = r[5]; o1.z = r[6]; o1.w = r[7];
    *(float4*)&out[idx] = o0;
    *(float4*)&out[idx + 4] = o1;
    if (oh) {
        *(uint4*)(oh + idx) = make_uint4(packh(r[0], r[1]), packh(r[2], r[3]),
                                         packh(r[4], r[5]), packh(r[6], r[7]));
    }
}

// ---------------- fused ln2 + oln1: y = LN(x + xl + LN(tmp)) ----------------
__launch_bounds__(256)
__global__ void ln2_oln1(const float* __restrict__ tmp,
                         const float* __restrict__ l2g, const float* __restrict__ l2b,
                         const float* __restrict__ x, const float* __restrict__ xl,
                         const float* __restrict__ o1g, const float* __restrict__ o1b,
                         float* __restrict__ y, __half* __restrict__ yh) {
    int row = blockIdx.x * 8 + (threadIdx.x >> 5);
    int lane = threadIdx.x & 31;
    size_t idx = (size_t)row * HH + lane * 8;
    int gcol = lane * 8;

    float v[8];
    float4 u0 = *(const float4*)&tmp[idx];
    float4 u1 = *(const float4*)&tmp[idx + 4];
    v[0]=u0.x; v[1]=u0.y; v[2]=u0.z; v[3]=u0.w;
    v[4]=u1.x; v[5]=u1.y; v[6]=u1.z; v[7]=u1.w;
    float s = 0.f, s2 = 0.f;
#pragma unroll
    for (int j = 0; j < 8; ++j) { s += v[j]; s2 += v[j]*v[j]; }
#pragma unroll
    for (int o = 16; o; o >>= 1) {
        s  += __shfl_xor_sync(0xFFFFFFFFu, s, o);
        s2 += __shfl_xor_sync(0xFFFFFFFFu, s2, o);
    }
    float mean = s * (1.f / HH);
    float rstd = rsqrtf(s2 * (1.f / HH) - mean * mean + 1e-5f);
    float4 g0 = *(const float4*)&l2g[gcol];
    float4 g1 = *(const float4*)&l2g[gcol + 4];
    float4 e0 = *(const float4*)&l2b[gcol];
    float4 e1 = *(const float4*)&l2b[gcol + 4];
    float h2[8];
    h2[0]=(v[0]-mean)*rstd*g0.x+e0.x; h2[1]=(v[1]-mean)*rstd*g0.y+e0.y;
    h2[2]=(v[2]-mean)*rstd*g0.z+e0.z; h2[3]=(v[3]-mean)*rstd*g0.w+e0.w;
    h2[4]=(v[4]-mean)*rstd*g1.x+e1.x; h2[5]=(v[5]-mean)*rstd*g1.y+e1.y;
    h2[6]=(v[6]-mean)*rstd*g1.z+e1.z; h2[7]=(v[7]-mean)*rstd*g1.w+e1.w;

    float4 xa0 = *(const float4*)&x[idx];
    float4 xa1 = *(const float4*)&x[idx + 4];
    float4 xb0 = *(const float4*)&xl[idx];
    float4 xb1 = *(const float4*)&xl[idx + 4];
    float u[8];
    u[0]=xa0.x+xb0.x+h2[0]; u[1]=xa0.y+xb0.y+h2[1];
    u[2]=xa0.z+xb0.z+h2[2]; u[3]=xa0.w+xb0.w+h2[3];
    u[4]=xa1.x+xb1.x+h2[4]; u[5]=xa1.y+xb1.y+h2[5];
    u[6]=xa1.z+xb1.z+h2[6]; u[7]=xa1.w+xb1.w+h2[7];
    s = 0.f; s2 = 0.f;
#pragma unroll
    for (int j = 0; j < 8; ++j) { s += u[j]; s2 += u[j]*u[j]; }
#pragma unroll
    for (int o = 16; o; o >>= 1) {
        s  += __shfl_xor_sync(0xFFFFFFFFu, s, o);
        s2 += __shfl_xor_sync(0xFFFFFFFFu, s2, o);
    }
    mean = s * (1.f / HH);
    rstd = rsqrtf(s2 * (1.f / HH) - mean * mean + 1e-5f);
    float4 og0 = *(const float4*)&o1g[gcol];
    float4 og1 = *(const float4*)&o1g[gcol + 4];
    float4 ob0 = *(const float4*)&o1b[gcol];
    float4 ob1 = *(const float4*)&o1b[gcol + 4];
    float r[8];
    r[0]=(u[0]-mean)*rstd*og0.x+ob0.x; r[1]=(u[1]-mean)*rstd*og0.y+ob0.y;
    r[2]=(u[2]-mean)*rstd*og0.z+ob0.z; r[3]=(u[3]-mean)*rstd*og0.w+ob0.w;
    r[4]=(u[4]-mean)*rstd*og1.x+ob1.x; r[5]=(u[5]-mean)*rstd*og1.y+ob1.y;
    r[6]=(u[6]-mean)*rstd*og1.z+ob1.z; r[7]=(u[7]-mean)*rstd*og1.w+ob1.w;
    float4 o0, o1;
    o0.x=r[0]; o0.y=r[1]; o0.z=r[2]; o0.w=r[3];
    o1.x=r[4]; o1.y=r[5]; o1.z=r[6]; o1.w=r[7];
    *(float4*)&y[idx] = o0;
    *(float4*)&y[idx + 4] = o1;
    *(uint4*)(yh + idx) = make_uint4(packh(r[0], r[1]), packh(r[2], r[3]),
                                     packh(r[4], r[5]), packh(r[6], r[7]));
}

// ---------------- host ----------------
static void* sym(const void* s) { void* p = nullptr; cudaGetSymbolAddress(&p, s); return p; }

static cudaStream_t s_s1, s_s2;
static cudaEvent_t  s_evA, s_evSW, s_evSPD, s_evGA;
static struct StreamInit {
    StreamInit() {
        cudaStreamCreateWithFlags(&s_s1, cudaStreamNonBlocking);
        cudaStreamCreateWithFlags(&s_s2, cudaStreamNonBlocking);
        cudaEventCreateWithFlags(&s_evA,   cudaEventDisableTiming);
        cudaEventCreateWithFlags(&s_evSW,  cudaEventDisableTiming);
        cudaEventCreateWithFlags(&s_evSPD, cudaEventDisableTiming);
        cudaEventCreateWithFlags(&s_evGA,  cudaEventDisableTiming);
    }
} s_streamInit;

extern "C" void kernel_launch(void* const* d_in, const int* in_sizes, int n_in,
                              void* d_out, int out_size) {
    const float* x      = (const float*)d_in[0];
    const float* gcn_w  = (const float*)d_in[1];
    const float* gcn_b  = (const float*)d_in[2];
    const float* qkv_w  = (const float*)d_in[3];
    const float* qkv_b  = (const float*)d_in[4];
    const float* proj_w = (const float*)d_in[5];
    const float* proj_b = (const float*)d_in[6];
    const float* ln1_g  = (const float*)d_in[7];
    const float* ln1_b  = (const float*)d_in[8];
    const float* ln2_g  = (const float*)d_in[9];
    const float* ln2_b  = (const float*)d_in[10];
    const float* ffn1_w = (const float*)d_in[11];
    const float* ffn1_b = (const float*)d_in[12];
    const float* ffn2_w = (const float*)d_in[13];
    const float* ffn2_b = (const float*)d_in[14];
    const float* bias_e = (const float*)d_in[15];
    const float* oln1_g = (const float*)d_in[16];
    const float* oln1_b = (const float*)d_in[17];
    const float* oln2_g = (const float*)d_in[18];
    const float* oln2_b = (const float*)d_in[19];
    const float* offn1_w= (const float*)d_in[20];
    const float* offn1_b= (const float*)d_in[21];
    const float* offn2_w= (const float*)d_in[22];
    const float* offn2_b= (const float*)d_in[23];
    const int*   ei     = (const int*)d_in[24];
    int E = in_sizes[24] / 2;

    float*    p_dinv = (float*)sym(g_dinv);
    float*    p_xw   = (float*)sym(g_xw);
    float*    p_xl   = (float*)sym(g_xl);
    uint32_t* p_adj  = (uint32_t*)sym(g_adj);
    uint32_t* p_R2   = (uint32_t*)sym(g_R2);
    uint32_t* p_R3   = (uint32_t*)sym(g_R3);
    uint32_t* p_R4   = (uint32_t*)sym(g_R4);
    uint32_t* p_R5   = (uint32_t*)sym(g_R5);
    unsigned char* p_dist = (unsigned char*)sym(g_dist);
    float*    p_qkv  = (float*)sym(g_qkv);
    float*    p_tmp  = (float*)sym(g_tmp);
    float*    p_h1   = (float*)sym(g_h1);
    float*    p_y    = (float*)sym(g_y);
    int*      p_cnt  = (int*)sym(g_cnt);
    int*      p_base = (int*)sym(g_base);
    int*      p_fill = (int*)sym(g_fillp);
    int*      p_esrc = (int*)sym(g_esrc);
    __half* x_h   = (__half*)sym(g_x_h);
    __half* at_h  = (__half*)sym(g_at_h);
    __half* h1_h  = (__half*)sym(g_h1_h);
    __half* y_h   = (__half*)sym(g_y_h);
    __half* mid_h = (__half*)sym(g_mid_h);
    __half* q_h   = (__half*)sym(g_q_h);
    __half* k_h   = (__half*)sym(g_k_h);
    __half* vt_h  = (__half*)sym(g_vt_h);
    __half* whi   = (__half*)sym(g_whi);
    float* out = (float*)d_out;

    const int SMEM  = 40960;
    const int ASMEM = 37888;
    cudaFuncSetAttribute(gemm_f16<0,0,0>, cudaFuncAttributeMaxDynamicSharedMemorySize, SMEM);
    cudaFuncSetAttribute(gemm_f16<0,1,0>, cudaFuncAttributeMaxDynamicSharedMemorySize, SMEM);
    cudaFuncSetAttribute(gemm_f16<1,0,1>, cudaFuncAttributeMaxDynamicSharedMemorySize, SMEM);
    cudaFuncSetAttribute(attn_mma, cudaFuncAttributeMaxDynamicSharedMemorySize, ASMEM);

    // --- default stream: counts + adjacency, then fork ---
    zero_prep<<<(GG * MM * 32 + 255) / 256, 256>>>(p_cnt, p_adj);
    edge_prep<<<(E + 255) / 256, 256>>>(ei, E, p_cnt, p_adj);
    cudaEventRecord(s_evA, 0);

    // --- s1: SPD chain ---
    cudaStreamWaitEvent(s_s1, s_evA, 0);
    spd_round<<<NN * 32 / 256, 256, 0, s_s1>>>(p_adj, p_adj, p_R2);
    spd_round<<<NN * 32 / 256, 256, 0, s_s1>>>(p_adj, p_R2, p_R3);
    spd_round<<<NN * 32 / 256, 256, 0, s_s1>>>(p_adj, p_R3, p_R4);
    spd_round<<<NN * 32 / 256, 256, 0, s_s1>>>(p_adj, p_R4, p_R5);
    spd_final<<<NN * 32 / 256, 256, 0, s_s1>>>(p_adj, p_R2, p_R3, p_R4, p_R5, p_dist);
    cudaEventRecord(s_evSPD, s_s1);

    // --- s2: edge CSR ---
    cudaStreamWaitEvent(s_s2, s_evA, 0);
    scan_kernel<<<1, 1024, 0, s_s2>>>(p_cnt, p_base, p_fill, p_dinv);
    fill_edges<<<(E + 255) / 256, 256, 0, s_s2>>>(ei, E, p_fill, p_esrc);

    // --- default stream: splits, then QKV directly (GCN moves to s2) ---
    splitx<<<(NN * HH / 4 + 255) / 256, 256>>>((const float4*)x, x_h, NN * HH / 4);
    splitw<<<(344064 + 255) / 256, 256>>>((const float4*)gcn_w, (const float4*)qkv_w,
        (const float4*)proj_w, (const float4*)ffn1_w, (const float4*)ffn2_w,
        (const float4*)offn1_w, (const float4*)offn2_w, whi);
    cudaEventRecord(s_evSW, 0);

    // --- s2: full GCN branch off the critical path ---
    cudaStreamWaitEvent(s_s2, s_evSW, 0);
    gemm_f16<0,0,0><<<dim3(NN/128, HH/128), 256, SMEM, s_s2>>>(x_h, whi + OFF_GCN,
        nullptr, nullptr, p_xw, nullptr, HH, HH);
    gcn_gather<<<NN / 4, 256, 0, s_s2>>>(p_xw, p_dinv, p_base, p_cnt, p_esrc, gcn_b, p_xl);
    cudaEventRecord(s_evGA, s_s2);

    // --- default stream: QKV + attention + FFN chain ---
    gemm_f16<0,0,0><<<dim3(NN/128, QKVD/128), 256, SMEM>>>(x_h, whi + OFF_QKV,
        qkv_b, nullptr, p_qkv, nullptr, HH, QKVD);
    qkv_prep<<<NN / 64, 256>>>(p_qkv, q_h, k_h, vt_h);

    cudaStreamWaitEvent(0, s_evSPD, 0);
    attn_mma<<<dim3(GG * NHEADS, MM / 128), 256, ASMEM>>>(q_h, k_h, vt_h, p_dist, bias_e, at_h);
    gemm_f16<0,1,0><<<dim3(NN/128, HH/128), 256, SMEM>>>(at_h, whi + OFF_PROJ,
        proj_b, x, p_tmp, nullptr, HH, HH);
    ln_kernel<<<NN / 8, 256>>>(p_tmp, nullptr, nullptr, ln1_g, ln1_b, p_h1, h1_h);
    gemm_f16<1,0,1><<<dim3(NN/128, FFND/128), 256, SMEM>>>(h1_h, whi + OFF_FFN1,
        ffn1_b, nullptr, nullptr, mid_h, HH, FFND);
    gemm_f16<0,1,0><<<dim3(NN/128, HH/128), 256, SMEM>>>(mid_h, whi + OFF_FFN2,
        ffn2_b, p_h1, p_tmp, nullptr, FFND, HH);

    // --- fused ln2 + GPS-combine oln1 (needs xl from s2) ---
    cudaStreamWaitEvent(0, s_evGA, 0);
    ln2_oln1<<<NN / 8, 256>>>(p_tmp, ln2_g, ln2_b, x, p_xl, oln1_g, oln1_b, p_y, y_h);
    gemm_f16<1,0,1><<<dim3(NN/128, FFND/128), 256, SMEM>>>(y_h, whi + OFF_OFFN1,
        offn1_b, nullptr, nullptr, mid_h, HH, FFND);
    gemm_f16<0,1,0><<<dim3(NN/128, HH/128), 256, SMEM>>>(mid_h, whi + OFF_OFFN2,
        offn2_b, p_y, p_tmp, nullptr, FFND, HH);
    ln_kernel<<<NN / 8, 256>>>(p_tmp, nullptr, nullptr, oln2_g, oln2_b, out, nullptr);
}

// round 17
// speedup vs baseline: 1.1188x; 1.0343x over previous
#include <cuda_runtime.h>
#include <cuda_fp16.h>
#include <cstdint>
#include <math.h>

#define GG 8
#define MM 1024
#define NN 8192
#define HH 256
#define NHEADS 8
#define HDIM 32
#define FFND 1024
#define QKVD 768

// ---------------- scratch ----------------
__device__ float    g_dinv[NN];
__device__ float    g_xw  [NN * HH];
__device__ float    g_xl  [NN * HH];
__device__ uint32_t g_adj [GG * MM * 32];
__device__ uint32_t g_R2  [GG * MM * 32];
__device__ uint32_t g_R3  [GG * MM * 32];
__device__ uint32_t g_R4  [GG * MM * 32];
__device__ uint32_t g_R5  [GG * MM * 32];
__device__ unsigned char g_dist[(size_t)GG * MM * MM];
__device__ float    g_qkv [(size_t)NN * QKVD];
__device__ float    g_tmp [NN * HH];
__device__ float    g_h1  [NN * HH];
__device__ float    g_y   [NN * HH];
__device__ int      g_cnt [NN];
__device__ int      g_base[NN];
__device__ int      g_fillp[NN];
__device__ int      g_esrc[262144];

#define AL16 __align__(16)
__device__ AL16 __half g_x_h [NN * HH];
__device__ AL16 __half g_at_h[NN * HH];
__device__ AL16 __half g_h1_h[NN * HH];
__device__ AL16 __half g_y_h [NN * HH];
__device__ AL16 __half g_mid_h[(size_t)NN * FFND];
__device__ AL16 __half g_q_h [NN * HH];
__device__ AL16 __half g_k_h [NN * HH];
__device__ AL16 __half g_vt_h[GG * NHEADS * HDIM * MM];
__device__ AL16 __half g_whi[1376256];
#define OFF_GCN   0
#define OFF_QKV   65536
#define OFF_PROJ  262144
#define OFF_FFN1  327680
#define OFF_FFN2  589824
#define OFF_OFFN1 851968
#define OFF_OFFN2 1114112

// ---------------- helpers ----------------
__device__ __forceinline__ uint32_t packh(float a, float b) {
    uint32_t r;
    asm("cvt.rn.f16x2.f32 %0, %1, %2;" : "=r"(r) : "f"(b), "f"(a));
    return r;
}
__device__ __forceinline__ float ex2f(float x) {
    float y; asm("ex2.approx.f32 %0, %1;" : "=f"(y) : "f"(x)); return y;
}
#define CP16(dst, src) asm volatile("cp.async.cg.shared.global [%0], [%1], 16;\n" :: "r"(dst), "l"(src))
#define MMAH(d, a0, a1, a2, a3, b0, b1) \
    asm volatile("mma.sync.aligned.m16n8k16.row.col.f32.f16.f16.f32 " \
                 "{%0,%1,%2,%3}, {%4,%5,%6,%7}, {%8,%9}, {%0,%1,%2,%3};" \
                 : "+f"(d[0]), "+f"(d[1]), "+f"(d[2]), "+f"(d[3]) \
                 : "r"(a0), "r"(a1), "r"(a2), "r"(a3), "r"(b0), "r"(b1))
#define LDSM4(r0, r1, r2, r3, addr) \
    asm volatile("ldmatrix.sync.aligned.m8n8.x4.shared.b16 {%0,%1,%2,%3}, [%4];" \
                 : "=r"(r0), "=r"(r1), "=r"(r2), "=r"(r3) : "r"(addr))

// ---------------- splits (plain fp16 cast) ----------------
__global__ void splitx(const float4* __restrict__ in, __half* __restrict__ hi, int n4) {
    int i = blockIdx.x * blockDim.x + threadIdx.x;
    if (i >= n4) return;
    float4 v = in[i];
    *(uint2*)(hi + i * 4) = make_uint2(packh(v.x, v.y), packh(v.z, v.w));
}
__global__ void splitw(const float4* w0, const float4* w1, const float4* w2, const float4* w3,
                       const float4* w4, const float4* w5, const float4* w6,
                       __half* __restrict__ hi) {
    int i = blockIdx.x * blockDim.x + threadIdx.x;
    if (i >= 344064) return;
    const float4* src; int base;
    if      (i < 16384)  { src = w0; base = 0; }
    else if (i < 65536)  { src = w1; base = 16384; }
    else if (i < 81920)  { src = w2; base = 65536; }
    else if (i < 147456) { src = w3; base = 81920; }
    else if (i < 212992) { src = w4; base = 147456; }
    else if (i < 278528) { src = w5; base = 212992; }
    else                 { src = w6; base = 278528; }
    float4 v = src[i - base];
    *(uint2*)(hi + (size_t)i * 4) = make_uint2(packh(v.x, v.y), packh(v.z, v.w));
}

// ---------------- graph prep ----------------
__global__ void zero_prep(int* __restrict__ cnt, uint32_t* __restrict__ adj) {
    int i = blockIdx.x * blockDim.x + threadIdx.x;
    if (i < GG * MM * 32) adj[i] = 0u;
    if (i < NN) cnt[i] = 0;
}
__global__ void edge_prep(const int* __restrict__ ei, int E, int* __restrict__ cnt,
                          uint32_t* __restrict__ adj) {
    int e = blockIdx.x * blockDim.x + threadIdx.x;
    if (e >= E) return;
    int s = ei[e], d = ei[E + e];
    atomicAdd(&cnt[d], 1);
    if (s == d || (s >> 10) != (d >> 10)) return;
    int g = s >> 10, ls = s & 1023, ld = d & 1023;
    atomicOr(&adj[((size_t)g * MM + ls) * 32 + (ld >> 5)], 1u << (ld & 31));
    atomicOr(&adj[((size_t)g * MM + ld) * 32 + (ls >> 5)], 1u << (ls & 31));
}
__global__ void scan_kernel(const int* __restrict__ cnt, int* __restrict__ base,
                            int* __restrict__ fillp, float* __restrict__ dinv) {
    __shared__ int wsum[32];
    int t = threadIdx.x;
    int v[8]; int s = 0;
#pragma unroll
    for (int k = 0; k < 8; ++k) { v[k] = s; s += cnt[t * 8 + k]; }
    int lane = t & 31, w = t >> 5;
    int tot = s, sc = s;
#pragma unroll
    for (int o = 1; o < 32; o <<= 1) {
        int n = __shfl_up_sync(0xFFFFFFFFu, sc, o);
        if (lane >= o) sc += n;
    }
    if (lane == 31) wsum[w] = sc;
    __syncthreads();
    if (w == 0) {
        int x = wsum[lane];
#pragma unroll
        for (int o = 1; o < 32; o <<= 1) {
            int n = __shfl_up_sync(0xFFFFFFFFu, x, o);
            if (lane >= o) x += n;
        }
        wsum[lane] = x;
    }
    __syncthreads();
    int excl = sc - tot + (w > 0 ? wsum[w - 1] : 0);
#pragma unroll
    for (int k = 0; k < 8; ++k) {
        int idx = t * 8 + k;
        int b = excl + v[k];
        base[idx] = b;
        fillp[idx] = b;
        dinv[idx] = rsqrtf((float)cnt[idx] + 1.0f);
    }
}
__global__ void fill_edges(const int* __restrict__ ei, int E, int* __restrict__ fillp,
                           int* __restrict__ esrc) {
    int e = blockIdx.x * blockDim.x + threadIdx.x;
    if (e >= E) return;
    int s = ei[e], d = ei[E + e];
    int pos = atomicAdd(&fillp[d], 1);
    esrc[pos] = s;
}
__launch_bounds__(256)
__global__ void gcn_gather(const float* __restrict__ xw, const float* __restrict__ dinv,
                           const int* __restrict__ base, const int* __restrict__ cnt,
                           const int* __restrict__ esrc, const float* __restrict__ gcn_b,
                           float* __restrict__ xl) {
    int node = blockIdx.x * 4 + (threadIdx.x >> 6);
    int c4 = (threadIdx.x & 63) * 4;
    float dd = dinv[node];
    float4 v0 = *(const float4*)&xw[(size_t)node * HH + c4];
    float ax = dd * v0.x, ay = dd * v0.y, az = dd * v0.z, aw = dd * v0.w;
    int b0 = __ldg(&base[node]);
    int n  = __ldg(&cnt[node]);
    int k = 0;
    for (; k + 4 <= n; k += 4) {
        int s0 = __ldg(&esrc[b0 + k]);
        int s1 = __ldg(&esrc[b0 + k + 1]);
        int s2 = __ldg(&esrc[b0 + k + 2]);
        int s3 = __ldg(&esrc[b0 + k + 3]);
        float w0 = __ldg(&dinv[s0]), w1 = __ldg(&dinv[s1]);
        float w2 = __ldg(&dinv[s2]), w3 = __ldg(&dinv[s3]);
        float4 a = *(const float4*)&xw[(size_t)s0 * HH + c4];
        float4 b = *(const float4*)&xw[(size_t)s1 * HH + c4];
        float4 c = *(const float4*)&xw[(size_t)s2 * HH + c4];
        float4 d = *(const float4*)&xw[(size_t)s3 * HH + c4];
        ax += w0 * a.x + w1 * b.x + w2 * c.x + w3 * d.x;
        ay += w0 * a.y + w1 * b.y + w2 * c.y + w3 * d.y;
        az += w0 * a.z + w1 * b.z + w2 * c.z + w3 * d.z;
        aw += w0 * a.w + w1 * b.w + w2 * c.w + w3 * d.w;
    }
    for (; k < n; ++k) {
        int s = __ldg(&esrc[b0 + k]);
        float ws = __ldg(&dinv[s]);
        float4 v = *(const float4*)&xw[(size_t)s * HH + c4];
        ax += ws * v.x; ay += ws * v.y; az += ws * v.z; aw += ws * v.w;
    }
    float4 bia = *(const float4*)&gcn_b[c4];
    float4 o;
    o.x = dd * ax + bia.x; o.y = dd * ay + bia.y;
    o.z = dd * az + bia.z; o.w = dd * aw + bia.w;
    *(float4*)&xl[(size_t)node * HH + c4] = o;
}

// ---------------- SPD: boolean matrix powers, warp-per-row, full-row early exit ----------------
__launch_bounds__(256)
__global__ void spd_round(const uint32_t* __restrict__ adj, const uint32_t* __restrict__ Rp,
                          uint32_t* __restrict__ Rn) {
    int gw = (blockIdx.x * 256 + threadIdx.x) >> 5;
    int lane = threadIdx.x & 31;
    int g = gw >> 10, i = gw & 1023;
    const uint32_t* Rg = Rp + (size_t)g * MM * 32;
    uint32_t nw = Rg[i * 32 + lane];
    // fixed point: a full row stays full (R monotone) -> skip expansion
    if (__ballot_sync(0xFFFFFFFFu, nw != 0xFFFFFFFFu) == 0u) {
        Rn[((size_t)g * MM + i) * 32 + lane] = nw;
        return;
    }
    uint32_t a = adj[((size_t)g * MM + i) * 32 + lane];
    for (int w = 0; w < 32; ++w) {
        uint32_t f = __shfl_sync(0xFFFFFFFFu, a, w);
        while (f) {
            int b = __ffs((int)f) - 1;
            f &= f - 1;
            nw |= Rg[(w * 32 + b) * 32 + lane];
        }
    }
    Rn[((size_t)g * MM + i) * 32 + lane] = nw;
}
__device__ __forceinline__ uint32_t nibspread(uint32_t r, int q) {
    return (((r >> (q * 4)) & 0xFu) * 0x00204081u) & 0x01010101u;
}
__launch_bounds__(256)
__global__ void spd_final(const uint32_t* __restrict__ R1, const uint32_t* __restrict__ R2,
                          const uint32_t* __restrict__ R3, const uint32_t* __restrict__ R4,
                          const uint32_t* __restrict__ R5, unsigned char* __restrict__ dist) {
    int idx = blockIdx.x * 256 + threadIdx.x;
    int row = idx >> 5, w = idx & 31;
    uint32_t r1 = R1[idx], r2 = R2[idx], r3 = R3[idx], r4 = R4[idx], r5 = R5[idx];
    unsigned char* drow = dist + (size_t)row * MM;
    uint4* dp = (uint4*)(drow + w * 32);
    uint32_t o[8];
#pragma unroll
    for (int q = 0; q < 8; ++q) {
        uint32_t s = nibspread(r1, q) + nibspread(r2, q) + nibspread(r3, q)
                   + nibspread(r4, q) + nibspread(r5, q);
        o[q] = 0x06060606u - s;
    }
    dp[0] = make_uint4(o[0], o[1], o[2], o[3]);
    dp[1] = make_uint4(o[4], o[5], o[6], o[7]);
    int i = row & 1023;
    if ((i >> 5) == w) drow[i] = 0;
}

// ---------------- fp16 GEMM 128x128 (ldmatrix, fp32 accum) ----------------
template <int GELU, int RES, int OUTF16>
__launch_bounds__(256, 2)
__global__ void gemm_f16(const __half* __restrict__ Ag, const __half* __restrict__ Whg,
                         const float* __restrict__ bias, const float* __restrict__ res,
                         float* __restrict__ C, __half* __restrict__ Ch, int K, int F) {
    extern __shared__ unsigned char smp[];
    const int STG = 20480;
    int m0 = blockIdx.x * 128, f0 = blockIdx.y * 128;
    int tid = threadIdx.x, lane = tid & 31, warp = tid >> 5;
    int g = lane >> 2, tg = lane & 3;
    int wm = (warp >> 2) * 64, wn = (warp & 3) * 32;
    uint32_t smem_base = (uint32_t)__cvta_generic_to_shared(smp);

    uint32_t aOff = (uint32_t)(wm + (lane & 15)) * 80 + (uint32_t)(lane >> 4) * 16;
    uint32_t bOff = (uint32_t)(wn + ((lane >> 4) << 3) + (lane & 7)) * 80
                  + (uint32_t)((lane >> 3) & 1) * 16;

    float acc[4][4][4];
#pragma unroll
    for (int a = 0; a < 4; ++a)
#pragma unroll
        for (int b = 0; b < 4; ++b)
#pragma unroll
            for (int c = 0; c < 4; ++c) acc[a][b][c] = 0.f;

    auto load_stage = [&](int s, int k0) {
        uint32_t db = smem_base + s * STG;
        const __half* srcs[2] = { Ag + (size_t)m0 * K + k0, Whg + (size_t)f0 * K + k0 };
#pragma unroll
        for (int arr = 0; arr < 2; ++arr) {
            const __half* bp = srcs[arr];
            uint32_t ab = db + arr * 10240;
#pragma unroll
            for (int c = 0; c < 2; ++c) {
                int t = tid + c * 256;
                int row = t >> 2, ch = t & 3;
                CP16(ab + row * 80 + ch * 16, bp + (size_t)row * K + ch * 8);
            }
        }
        asm volatile("cp.async.commit_group;\n" ::);
    };

    int nk = K >> 5;
    load_stage(0, 0);
    for (int kc = 0; kc < nk; ++kc) {
        if (kc + 1 < nk) {
            load_stage((kc + 1) & 1, (kc + 1) << 5);
            asm volatile("cp.async.wait_group 1;\n" ::);
        } else {
            asm volatile("cp.async.wait_group 0;\n" ::);
        }
        __syncthreads();

        uint32_t stg = smem_base + (kc & 1) * STG;
        uint32_t aB  = stg + aOff;
        uint32_t whB = stg + 10240 + bOff;
#pragma unroll
        for (int ks = 0; ks < 2; ++ks) {
            uint32_t bh[4][2];
            LDSM4(bh[0][0], bh[0][1], bh[1][0], bh[1][1], whB + ks * 32);
            LDSM4(bh[2][0], bh[2][1], bh[3][0], bh[3][1], whB + 1280 + ks * 32);
#pragma unroll
            for (int mt = 0; mt < 4; ++mt) {
                uint32_t a0, a1, a2, a3;
                LDSM4(a0, a1, a2, a3, aB + mt * 1280 + ks * 32);
#pragma unroll
                for (int nt = 0; nt < 4; ++nt)
                    MMAH(acc[mt][nt], a0, a1, a2, a3, bh[nt][0], bh[nt][1]);
            }
        }
        __syncthreads();
    }

#pragma unroll
    for (int mt = 0; mt < 4; ++mt) {
#pragma unroll
        for (int half = 0; half < 2; ++half) {
            int row = m0 + wm + mt * 16 + g + half * 8;
#pragma unroll
            for (int nt = 0; nt < 4; ++nt) {
                int col = f0 + wn + nt * 8 + tg * 2;
                float v0 = acc[mt][nt][half * 2 + 0];
                float v1 = acc[mt][nt][half * 2 + 1];
                if (bias) { v0 += bias[col]; v1 += bias[col + 1]; }
                if (GELU) { v0 = v0 * normcdff(v0); v1 = v1 * normcdff(v1); }
                if (RES)  { v0 += res[(size_t)row * F + col]; v1 += res[(size_t)row * F + col + 1]; }
                if (OUTF16) {
                    *(uint32_t*)(Ch + (size_t)row * F + col) = packh(v0, v1);
                } else {
                    float2 o; o.x = v0; o.y = v1;
                    *(float2*)(C + (size_t)row * F + col) = o;
                }
            }
        }
    }
}

// ---------------- qkv prepass ----------------
__launch_bounds__(256)
__global__ void qkv_prep(const float* __restrict__ qkv,
                         __half* __restrict__ qh, __half* __restrict__ kh,
                         __half* __restrict__ vth) {
    __shared__ float vsm[64][33];
    int nb = blockIdx.x * 64;
    int g = nb >> 10;
    int jb = nb & 1023;
    int tid = threadIdx.x;
    const float scale = 0.17677669529663687f;

#pragma unroll
    for (int it = 0; it < 32; ++it) {
        int flat = tid + it * 256;
        int row = flat >> 7, c4 = flat & 127;
        int node = nb + row;
        float4 v = *(const float4*)&qkv[(size_t)node * QKVD + c4 * 4];
        int c = c4 * 4;
        if (c < 256) {
            *(uint2*)(qh + (size_t)node * HH + c) =
                make_uint2(packh(v.x * scale, v.y * scale), packh(v.z * scale, v.w * scale));
        } else {
            *(uint2*)(kh + (size_t)node * HH + c - 256) =
                make_uint2(packh(v.x, v.y), packh(v.z, v.w));
        }
    }

    for (int h = 0; h < NHEADS; ++h) {
        __syncthreads();
#pragma unroll
        for (int it = 0; it < 2; ++it) {
            int flat = tid + it * 256;
            int row = flat >> 3, c4 = flat & 7;
            float4 v = *(const float4*)&qkv[(size_t)(nb + row) * QKVD + 512 + h * 32 + c4 * 4];
            vsm[row][c4 * 4 + 0] = v.x;
            vsm[row][c4 * 4 + 1] = v.y;
            vsm[row][c4 * 4 + 2] = v.z;
            vsm[row][c4 * 4 + 3] = v.w;
        }
        __syncthreads();
        int d = tid >> 3, j0 = (tid & 7) * 8;
        uint32_t hw[4];
#pragma unroll
        for (int p = 0; p < 4; ++p)
            hw[p] = packh(vsm[j0 + p * 2 + 0][d], vsm[j0 + p * 2 + 1][d]);
        size_t off = ((size_t)(g * NHEADS + h) * HDIM + d) * MM + jb + j0;
        *(uint4*)(vth + off) = make_uint4(hw[0], hw[1], hw[2], hw[3]);
    }
}

// ---------------- flash attention (fp16 single K/V, fp32 accum) ----------------
__launch_bounds__(256)
__global__ void attn_mma(const __half* __restrict__ qh, const __half* __restrict__ kh,
                         const __half* __restrict__ vth,
                         const unsigned char* __restrict__ dist, const float* __restrict__ bias_emb,
                         __half* __restrict__ oh) {
    extern __shared__ unsigned char smp[];
    const int STG = 18944;
    __shared__ float btab[8];
    int gh = blockIdx.x;
    int g = gh >> 3, h = gh & 7;
    int i0 = blockIdx.y * 128;
    int tid = threadIdx.x, lane = tid & 31, warp = tid >> 5;
    int r = lane >> 2, tg = lane & 3;
    if (tid < 7) btab[tid] = bias_emb[tid];
    uint32_t sb = (uint32_t)__cvta_generic_to_shared(smp);
    const float L2E = 1.44269504f;

    int rowA = i0 + warp * 16 + r;
    int rowB = rowA + 8;
    uint32_t qf[2][4];
#pragma unroll
    for (int kc = 0; kc < 2; ++kc) {
        size_t baseA = (size_t)(g * MM + rowA) * HH + h * HDIM + kc * 16 + tg * 2;
        size_t baseB = (size_t)(g * MM + rowB) * HH + h * HDIM + kc * 16 + tg * 2;
        qf[kc][0] = *(const uint32_t*)(qh + baseA);
        qf[kc][1] = *(const uint32_t*)(qh + baseB);
        qf[kc][2] = *(const uint32_t*)(qh + baseA + 8);
        qf[kc][3] = *(const uint32_t*)(qh + baseB + 8);
    }

    float acc_o[4][4];
#pragma unroll
    for (int a = 0; a < 4; ++a)
#pragma unroll
        for (int b = 0; b < 4; ++b) acc_o[a][b] = 0.f;
    float mA = -1e30f, mB = -1e30f, lA = 0.f, lB = 0.f;

    const unsigned char* drowA = dist + ((size_t)(g * MM + rowA)) * MM;
    const unsigned char* drowB = dist + ((size_t)(g * MM + rowB)) * MM;

    auto load_stage = [&](int s, int j0) {
        uint32_t db = sb + s * STG;
#pragma unroll
        for (int c = 0; c < 2; ++c) {
            int t = tid + c * 256;
            int row = t >> 2, ch = t & 3;
            const __half* src = kh + (size_t)(g * MM + j0 + row) * HH + h * HDIM + ch * 8;
            CP16(db + row * 80 + ch * 16, src);
        }
#pragma unroll
        for (int c = 0; c < 2; ++c) {
            int t = tid + c * 256;
            int row = t >> 4, ch = t & 15;
            size_t off = ((size_t)(gh) * HDIM + row) * MM + j0 + ch * 8;
            CP16(db + 10240 + row * 272 + ch * 16, vth + off);
        }
        asm volatile("cp.async.commit_group;\n" ::);
    };

    load_stage(0, 0);
    for (int ch = 0; ch < 8; ++ch) {
        int j0 = ch * 128;
        if (ch < 7) {
            load_stage((ch + 1) & 1, j0 + 128);
            asm volatile("cp.async.wait_group 1;\n" ::);
        } else {
            asm volatile("cp.async.wait_group 0;\n" ::);
        }
        __syncthreads();

        const uint32_t* KH = (const uint32_t*)(smp + (ch & 1) * STG);
        const uint32_t* VH = KH + 2560;

        float acc_s[16][4];
#pragma unroll
        for (int nt = 0; nt < 16; ++nt)
#pragma unroll
            for (int c = 0; c < 4; ++c) acc_s[nt][c] = 0.f;
#pragma unroll
        for (int kc = 0; kc < 2; ++kc) {
#pragma unroll
            for (int nt = 0; nt < 16; ++nt) {
                int idx = (nt * 8 + r) * 20 + kc * 8 + tg;
                MMAH(acc_s[nt], qf[kc][0], qf[kc][1], qf[kc][2], qf[kc][3],
                     KH[idx], KH[idx + 4]);
            }
        }

        float cmA = -1e30f, cmB = -1e30f;
#pragma unroll
        for (int nt = 0; nt < 16; ++nt) {
            uchar2 dA = *(const uchar2*)(drowA + j0 + nt * 8 + tg * 2);
            uchar2 dB = *(const uchar2*)(drowB + j0 + nt * 8 + tg * 2);
            acc_s[nt][0] += btab[dA.x];
            acc_s[nt][1] += btab[dA.y];
            acc_s[nt][2] += btab[dB.x];
            acc_s[nt][3] += btab[dB.y];
            cmA = fmaxf(cmA, fmaxf(acc_s[nt][0], acc_s[nt][1]));
            cmB = fmaxf(cmB, fmaxf(acc_s[nt][2], acc_s[nt][3]));
        }
        cmA = fmaxf(cmA, __shfl_xor_sync(0xFFFFFFFFu, cmA, 1));
        cmA = fmaxf(cmA, __shfl_xor_sync(0xFFFFFFFFu, cmA, 2));
        cmB = fmaxf(cmB, __shfl_xor_sync(0xFFFFFFFFu, cmB, 1));
        cmB = fmaxf(cmB, __shfl_xor_sync(0xFFFFFFFFu, cmB, 2));

        float mAn = fmaxf(mA, cmA), mBn = fmaxf(mB, cmB);
        float corrA = ex2f((mA - mAn) * L2E);
        float corrB = ex2f((mB - mBn) * L2E);
        mA = mAn; mB = mBn;

        uint32_t ph0[16], ph1[16];
        float lsA = 0.f, lsB = 0.f;
#pragma unroll
        for (int nt = 0; nt < 16; ++nt) {
            float p0 = ex2f((acc_s[nt][0] - mA) * L2E);
            float p1 = ex2f((acc_s[nt][1] - mA) * L2E);
            float p2 = ex2f((acc_s[nt][2] - mB) * L2E);
            float p3 = ex2f((acc_s[nt][3] - mB) * L2E);
            lsA += p0 + p1; lsB += p2 + p3;
            ph0[nt] = packh(p0, p1);
            ph1[nt] = packh(p2, p3);
        }
        lsA += __shfl_xor_sync(0xFFFFFFFFu, lsA, 1);
        lsA += __shfl_xor_sync(0xFFFFFFFFu, lsA, 2);
        lsB += __shfl_xor_sync(0xFFFFFFFFu, lsB, 1);
        lsB += __shfl_xor_sync(0xFFFFFFFFu, lsB, 2);
        lA = lA * corrA + lsA;
        lB = lB * corrB + lsB;

#pragma unroll
        for (int nto = 0; nto < 4; ++nto) {
            acc_o[nto][0] *= corrA; acc_o[nto][1] *= corrA;
            acc_o[nto][2] *= corrB; acc_o[nto][3] *= corrB;
        }

#pragma unroll
        for (int kc = 0; kc < 8; ++kc) {
            uint32_t a0 = ph0[2 * kc], a1 = ph1[2 * kc], a2 = ph0[2 * kc + 1], a3 = ph1[2 * kc + 1];
#pragma unroll
            for (int nto = 0; nto < 4; ++nto) {
                int idx = (nto * 8 + r) * 68 + kc * 8 + tg;
                MMAH(acc_o[nto], a0, a1, a2, a3, VH[idx], VH[idx + 4]);
            }
        }
        __syncthreads();
    }

    float invA = 1.f / lA, invB = 1.f / lB;
#pragma unroll
    for (int nto = 0; nto < 4; ++nto) {
        int col = h * HDIM + nto * 8 + tg * 2;
        *(uint32_t*)(oh + (size_t)(g * MM + rowA) * HH + col) =
            packh(acc_o[nto][0] * invA, acc_o[nto][1] * invA);
        *(uint32_t*)(oh + (size_t)(g * MM + rowB) * HH + col) =
            packh(acc_o[nto][2] * invB, acc_o[nto][3] * invB);
    }
}

// ---------------- LayerNorm: warp-per-row, 8 rows per CTA ----------------
__launch_bounds__(256)
__global__ void ln_kernel(const float* __restrict__ a, const float* __restrict__ b,
                          const float* __restrict__ c, const float* __restrict__ gam,
                          const float* __restrict__ bet, float* __restrict__ out,
                          __half* __restrict__ oh) {
    int row = blockIdx.x * 8 + (threadIdx.x >> 5);
    int lane = threadIdx.x & 31;
    size_t idx = (size_t)row * HH + lane * 8;
    float v[8];
    float4 u0 = *(const float4*)&a[idx];
    float4 u1 = *(const float4*)&a[idx + 4];
    v[0] = u0.x; v[1] = u0.y; v[2] = u0.z; v[3] = u0.w;
    v[4] = u1.x; v[5] = u1.y; v[6] = u1.z; v[7] = u1.w;
    if (b) {
        float4 b0 = *(const float4*)&b[idx];
        float4 b1 = *(const float4*)&b[idx + 4];
        v[0] += b0.x; v[1] += b0.y; v[2] += b0.z; v[3] += b0.w;
        v[4] += b1.x; v[5] += b1.y; v[6] += b1.z; v[7] += b1.w;
    }
    if (c) {
        float4 c0 = *(const float4*)&c[idx];
        float4 c1 = *(const float4*)&c[idx + 4];
        v[0] += c0.x; v[1] += c0.y; v[2] += c0.z; v[3] += c0.w;
        v[4] += c1.x; v[5] += c1.y; v[6] += c1.z; v[7] += c1.w;
    }
    float s = 0.f, s2 = 0.f;
#pragma unroll
    for (int j = 0; j < 8; ++j) { s += v[j]; s2 += v[j] * v[j]; }
#pragma unroll
    for (int o = 16; o; o >>= 1) {
        s  += __shfl_xor_sync(0xFFFFFFFFu, s, o);
        s2 += __shfl_xor_sync(0xFFFFFFFFu, s2, o);
    }
    float mean = s * (1.f / HH);
    float var  = s2 * (1.f / HH) - mean * mean;
    float rstd = rsqrtf(var + 1e-5f);
    int gcol = lane * 8;
    float4 g0 = *(const float4*)&gam[gcol];
    float4 g1 = *(const float4*)&gam[gcol + 4];
    float4 e0 = *(const float4*)&bet[gcol];
    float4 e1 = *(const float4*)&bet[gcol + 4];
    float r[8];
    r[0] = (v[0] - mean) * rstd * g0.x + e0.x;
    r[1] = (v[1] - mean) * rstd * g0.y + e0.y;
    r[2] = (v[2] - mean) * rstd * g0.z + e0.z;
    r[3] = (v[3] - mean) * rstd * g0.w + e0.w;
    r[4] = (v[4] - mean) * rstd * g1.x + e1.x;
    r[5] = (v[5] - mean) * rstd * g1.y + e1.y;
    r[6] = (v[6] - mean) * rstd * g1.z + e1.z;
    r[7] = (v[7] - mean) * rstd * g1.w + e1.w;
    float4 o0, o1;
    o0.x = r[0]; o0.y = r[1]; o0.z = r[2]; o0.w = r[3];
    o1.x = r[4]; o1.y = r[5]; o1.z = r[6]; o1.w = r[7];
    *(float4*)&out[idx] = o0;
    *(float4*)&out[idx + 4] = o1;
    if (oh) {
        *(uint4*)(oh + idx) = make_uint4(packh(r[0], r[1]), packh(r[2], r[3]),
                                         packh(r[4], r[5]), packh(r[6], r[7]));
    }
}

// ---------------- fused ln2 + oln1: y = LN(x + xl + LN(tmp)) ----------------
__launch_bounds__(256)
__global__ void ln2_oln1(const float* __restrict__ tmp,
                         const float* __restrict__ l2g, const float* __restrict__ l2b,
                         const float* __restrict__ x, const float* __restrict__ xl,
                         const float* __restrict__ o1g, const float* __restrict__ o1b,
                         float* __restrict__ y, __half* __restrict__ yh) {
    int row = blockIdx.x * 8 + (threadIdx.x >> 5);
    int lane = threadIdx.x & 31;
    size_t idx = (size_t)row * HH + lane * 8;
    int gcol = lane * 8;

    float v[8];
    float4 u0 = *(const float4*)&tmp[idx];
    float4 u1 = *(const float4*)&tmp[idx + 4];
    v[0]=u0.x; v[1]=u0.y; v[2]=u0.z; v[3]=u0.w;
    v[4]=u1.x; v[5]=u1.y; v[6]=u1.z; v[7]=u1.w;
    float s = 0.f, s2 = 0.f;
#pragma unroll
    for (int j = 0; j < 8; ++j) { s += v[j]; s2 += v[j]*v[j]; }
#pragma unroll
    for (int o = 16; o; o >>= 1) {
        s  += __shfl_xor_sync(0xFFFFFFFFu, s, o);
        s2 += __shfl_xor_sync(0xFFFFFFFFu, s2, o);
    }
    float mean = s * (1.f / HH);
    float rstd = rsqrtf(s2 * (1.f / HH) - mean * mean + 1e-5f);
    float4 g0 = *(const float4*)&l2g[gcol];
    float4 g1 = *(const float4*)&l2g[gcol + 4];
    float4 e0 = *(const float4*)&l2b[gcol];
    float4 e1 = *(const float4*)&l2b[gcol + 4];
    float h2[8];
    h2[0]=(v[0]-mean)*rstd*g0.x+e0.x; h2[1]=(v[1]-mean)*rstd*g0.y+e0.y;
    h2[2]=(v[2]-mean)*rstd*g0.z+e0.z; h2[3]=(v[3]-mean)*rstd*g0.w+e0.w;
    h2[4]=(v[4]-mean)*rstd*g1.x+e1.x; h2[5]=(v[5]-mean)*rstd*g1.y+e1.y;
    h2[6]=(v[6]-mean)*rstd*g1.z+e1.z; h2[7]=(v[7]-mean)*rstd*g1.w+e1.w;

    float4 xa0 = *(const float4*)&x[idx];
    float4 xa1 = *(const float4*)&x[idx + 4];
    float4 xb0 = *(const float4*)&xl[idx];
    float4 xb1 = *(const float4*)&xl[idx + 4];
    float u[8];
    u[0]=xa0.x+xb0.x+h2[0]; u[1]=xa0.y+xb0.y+h2[1];
    u[2]=xa0.z+xb0.z+h2[2]; u[3]=xa0.w+xb0.w+h2[3];
    u[4]=xa1.x+xb1.x+h2[4]; u[5]=xa1.y+xb1.y+h2[5];
    u[6]=xa1.z+xb1.z+h2[6]; u[7]=xa1.w+xb1.w+h2[7];
    s = 0.f; s2 = 0.f;
#pragma unroll
    for (int j = 0; j < 8; ++j) { s += u[j]; s2 += u[j]*u[j]; }
#pragma unroll
    for (int o = 16; o; o >>= 1) {
        s  += __shfl_xor_sync(0xFFFFFFFFu, s, o);
        s2 += __shfl_xor_sync(0xFFFFFFFFu, s2, o);
    }
    mean = s * (1.f / HH);
    rstd = rsqrtf(s2 * (1.f / HH) - mean * mean + 1e-5f);
    float4 og0 = *(const float4*)&o1g[gcol];
    float4 og1 = *(const float4*)&o1g[gcol + 4];
    float4 ob0 = *(const float4*)&o1b[gcol];
    float4 ob1 = *(const float4*)&o1b[gcol + 4];
    float r[8];
    r[0]=(u[0]-mean)*rstd*og0.x+ob0.x; r[1]=(u[1]-mean)*rstd*og0.y+ob0.y;
    r[2]=(u[2]-mean)*rstd*og0.z+ob0.z; r[3]=(u[3]-mean)*rstd*og0.w+ob0.w;
    r[4]=(u[4]-mean)*rstd*og1.x+ob1.x; r[5]=(u[5]-mean)*rstd*og1.y+ob1.y;
    r[6]=(u[6]-mean)*rstd*og1.z+ob1.z; r[7]=(u[7]-mean)*rstd*og1.w+ob1.w;
    float4 o0, o1;
    o0.x=r[0]; o0.y=r[1]; o0.z=r[2]; o0.w=r[3];
    o1.x=r[4]; o1.y=r[5]; o1.z=r[6]; o1.w=r[7];
    *(float4*)&y[idx] = o0;
    *(float4*)&y[idx + 4] = o1;
    *(uint4*)(yh + idx) = make_uint4(packh(r[0], r[1]), packh(r[2], r[3]),
                                     packh(r[4], r[5]), packh(r[6], r[7]));
}

// ---------------- host ----------------
static void* sym(const void* s) { void* p = nullptr; cudaGetSymbolAddress(&p, s); return p; }

static cudaStream_t s_s1, s_s2;
static cudaEvent_t  s_evA, s_evSW, s_evSPD, s_evGA;
static struct StreamInit {
    StreamInit() {
        cudaStreamCreateWithFlags(&s_s1, cudaStreamNonBlocking);
        cudaStreamCreateWithFlags(&s_s2, cudaStreamNonBlocking);
        cudaEventCreateWithFlags(&s_evA,   cudaEventDisableTiming);
        cudaEventCreateWithFlags(&s_evSW,  cudaEventDisableTiming);
        cudaEventCreateWithFlags(&s_evSPD, cudaEventDisableTiming);
        cudaEventCreateWithFlags(&s_evGA,  cudaEventDisableTiming);
    }
} s_streamInit;

extern "C" void kernel_launch(void* const* d_in, const int* in_sizes, int n_in,
                              void* d_out, int out_size) {
    const float* x      = (const float*)d_in[0];
    const float* gcn_w  = (const float*)d_in[1];
    const float* gcn_b  = (const float*)d_in[2];
    const float* qkv_w  = (const float*)d_in[3];
    const float* qkv_b  = (const float*)d_in[4];
    const float* proj_w = (const float*)d_in[5];
    const float* proj_b = (const float*)d_in[6];
    const float* ln1_g  = (const float*)d_in[7];
    const float* ln1_b  = (const float*)d_in[8];
    const float* ln2_g  = (const float*)d_in[9];
    const float* ln2_b  = (const float*)d_in[10];
    const float* ffn1_w = (const float*)d_in[11];
    const float* ffn1_b = (const float*)d_in[12];
    const float* ffn2_w = (const float*)d_in[13];
    const float* ffn2_b = (const float*)d_in[14];
    const float* bias_e = (const float*)d_in[15];
    const float* oln1_g = (const float*)d_in[16];
    const float* oln1_b = (const float*)d_in[17];
    const float* oln2_g = (const float*)d_in[18];
    const float* oln2_b = (const float*)d_in[19];
    const float* offn1_w= (const float*)d_in[20];
    const float* offn1_b= (const float*)d_in[21];
    const float* offn2_w= (const float*)d_in[22];
    const float* offn2_b= (const float*)d_in[23];
    const int*   ei     = (const int*)d_in[24];
    int E = in_sizes[24] / 2;

    float*    p_dinv = (float*)sym(g_dinv);
    float*    p_xw   = (float*)sym(g_xw);
    float*    p_xl   = (float*)sym(g_xl);
    uint32_t* p_adj  = (uint32_t*)sym(g_adj);
    uint32_t* p_R2   = (uint32_t*)sym(g_R2);
    uint32_t* p_R3   = (uint32_t*)sym(g_R3);
    uint32_t* p_R4   = (uint32_t*)sym(g_R4);
    uint32_t* p_R5   = (uint32_t*)sym(g_R5);
    unsigned char* p_dist = (unsigned char*)sym(g_dist);
    float*    p_qkv  = (float*)sym(g_qkv);
    float*    p_tmp  = (float*)sym(g_tmp);
    float*    p_h1   = (float*)sym(g_h1);
    float*    p_y    = (float*)sym(g_y);
    int*      p_cnt  = (int*)sym(g_cnt);
    int*      p_base = (int*)sym(g_base);
    int*      p_fill = (int*)sym(g_fillp);
    int*      p_esrc = (int*)sym(g_esrc);
    __half* x_h   = (__half*)sym(g_x_h);
    __half* at_h  = (__half*)sym(g_at_h);
    __half* h1_h  = (__half*)sym(g_h1_h);
    __half* y_h   = (__half*)sym(g_y_h);
    __half* mid_h = (__half*)sym(g_mid_h);
    __half* q_h   = (__half*)sym(g_q_h);
    __half* k_h   = (__half*)sym(g_k_h);
    __half* vt_h  = (__half*)sym(g_vt_h);
    __half* whi   = (__half*)sym(g_whi);
    float* out = (float*)d_out;

    const int SMEM  = 40960;
    const int ASMEM = 37888;
    cudaFuncSetAttribute(gemm_f16<0,0,0>, cudaFuncAttributeMaxDynamicSharedMemorySize, SMEM);
    cudaFuncSetAttribute(gemm_f16<0,1,0>, cudaFuncAttributeMaxDynamicSharedMemorySize, SMEM);
    cudaFuncSetAttribute(gemm_f16<1,0,1>, cudaFuncAttributeMaxDynamicSharedMemorySize, SMEM);
    cudaFuncSetAttribute(attn_mma, cudaFuncAttributeMaxDynamicSharedMemorySize, ASMEM);

    // --- default stream: counts + adjacency, then fork ---
    zero_prep<<<(GG * MM * 32 + 255) / 256, 256>>>(p_cnt, p_adj);
    edge_prep<<<(E + 255) / 256, 256>>>(ei, E, p_cnt, p_adj);
    cudaEventRecord(s_evA, 0);

    // --- s1: SPD chain (rounds 3-4 mostly skipped via full-row fixpoint) ---
    cudaStreamWaitEvent(s_s1, s_evA, 0);
    spd_round<<<NN * 32 / 256, 256, 0, s_s1>>>(p_adj, p_adj, p_R2);
    spd_round<<<NN * 32 / 256, 256, 0, s_s1>>>(p_adj, p_R2, p_R3);
    spd_round<<<NN * 32 / 256, 256, 0, s_s1>>>(p_adj, p_R3, p_R4);
    spd_round<<<NN * 32 / 256, 256, 0, s_s1>>>(p_adj, p_R4, p_R5);
    spd_final<<<NN * 32 / 256, 256, 0, s_s1>>>(p_adj, p_R2, p_R3, p_R4, p_R5, p_dist);
    cudaEventRecord(s_evSPD, s_s1);

    // --- s2: edge CSR ---
    cudaStreamWaitEvent(s_s2, s_evA, 0);
    scan_kernel<<<1, 1024, 0, s_s2>>>(p_cnt, p_base, p_fill, p_dinv);
    fill_edges<<<(E + 255) / 256, 256, 0, s_s2>>>(ei, E, p_fill, p_esrc);

    // --- default stream: splits, then QKV directly ---
    splitx<<<(NN * HH / 4 + 255) / 256, 256>>>((const float4*)x, x_h, NN * HH / 4);
    splitw<<<(344064 + 255) / 256, 256>>>((const float4*)gcn_w, (const float4*)qkv_w,
        (const float4*)proj_w, (const float4*)ffn1_w, (const float4*)ffn2_w,
        (const float4*)offn1_w, (const float4*)offn2_w, whi);
    cudaEventRecord(s_evSW, 0);

    // --- s2: full GCN branch off the critical path ---
    cudaStreamWaitEvent(s_s2, s_evSW, 0);
    gemm_f16<0,0,0><<<dim3(NN/128, HH/128), 256, SMEM, s_s2>>>(x_h, whi + OFF_GCN,
        nullptr, nullptr, p_xw, nullptr, HH, HH);
    gcn_gather<<<NN / 4, 256, 0, s_s2>>>(p_xw, p_dinv, p_base, p_cnt, p_esrc, gcn_b, p_xl);
    cudaEventRecord(s_evGA, s_s2);

    // --- default stream: QKV + attention + FFN chain ---
    gemm_f16<0,0,0><<<dim3(NN/128, QKVD/128), 256, SMEM>>>(x_h, whi + OFF_QKV,
        qkv_b, nullptr, p_qkv, nullptr, HH, QKVD);
    qkv_prep<<<NN / 64, 256>>>(p_qkv, q_h, k_h, vt_h);

    cudaStreamWaitEvent(0, s_evSPD, 0);
    attn_mma<<<dim3(GG * NHEADS, MM / 128), 256, ASMEM>>>(q_h, k_h, vt_h, p_dist, bias_e, at_h);
    gemm_f16<0,1,0><<<dim3(NN/128, HH/128), 256, SMEM>>>(at_h, whi + OFF_PROJ,
        proj_b, x, p_tmp, nullptr, HH, HH);
    ln_kernel<<<NN / 8, 256>>>(p_tmp, nullptr, nullptr, ln1_g, ln1_b, p_h1, h1_h);
    gemm_f16<1,0,1><<<dim3(NN/128, FFND/128), 256, SMEM>>>(h1_h, whi + OFF_FFN1,
        ffn1_b, nullptr, nullptr, mid_h, HH, FFND);
    gemm_f16<0,1,0><<<dim3(NN/128, HH/128), 256, SMEM>>>(mid_h, whi + OFF_FFN2,
        ffn2_b, p_h1, p_tmp, nullptr, FFND, HH);

    // --- fused ln2 + GPS-combine oln1 (needs xl from s2) ---
    cudaStreamWaitEvent(0, s_evGA, 0);
    ln2_oln1<<<NN / 8, 256>>>(p_tmp, ln2_g, ln2_b, x, p_xl, oln1_g, oln1_b, p_y, y_h);
    gemm_f16<1,0,1><<<dim3(NN/128, FFND/128), 256, SMEM>>>(y_h, whi + OFF_OFFN1,
        offn1_b, nullptr, nullptr, mid_h, HH, FFND);
    gemm_f16<0,1,0><<<dim3(NN/128, HH/128), 256, SMEM>>>(mid_h, whi + OFF_OFFN2,
        offn2_b, p_y, p_tmp, nullptr, FFND, HH);
    ln_kernel<<<NN / 8, 256>>>(p_tmp, nullptr, nullptr, oln2_g, oln2_b, out, nullptr);
}